// round 14
// baseline (speedup 1.0000x reference)
#include <cuda_runtime.h>
#include <cuda_fp16.h>
#include <cstdint>

// Problem constants
#define B_SZ    1024
#define K_SEQ   16
#define D_DIM   1024
#define H_NUM   16
#define HD      64
#define NIRR    16

#define GM      (B_SZ * K_SEQ)   // 16384
#define GN      D_DIM            // 1024
#define GK      D_DIM            // 1024
#define N3      (3 * GN)         // 3072

// ---------------- scratch (device globals: no allocations allowed) ----------
__device__ __half g_xh[GM * GK];
__device__ __half g_qkv[(size_t)GM * N3];   // merged Q|K|V, pitch 3072
__device__ __half g_th[GM * GN];
__device__ __half g_wt[4][GK * GN];         // transposed weights [N][K], fp16
__device__ float  g_bias[N3];               // concat bq|bk|bv

// ---------------- helpers -----------------------------------------------------
__device__ __forceinline__ uint32_t smem_u32(const void* p) {
    uint32_t a;
    asm("{ .reg .u64 t; cvta.to.shared.u64 t, %1; cvt.u32.u64 %0, t; }"
        : "=r"(a) : "l"(p));
    return a;
}
__device__ __forceinline__ void cp16(uint32_t daddr, const void* g) {
    asm volatile("cp.async.cg.shared.global [%0], [%1], 16;\n"
                 :: "r"(daddr), "l"(g) : "memory");
}
__device__ __forceinline__ void ldsm4(uint32_t& r0, uint32_t& r1,
                                      uint32_t& r2, uint32_t& r3, uint32_t a) {
    asm volatile("ldmatrix.sync.aligned.m8n8.x4.shared.b16 {%0,%1,%2,%3}, [%4];"
                 : "=r"(r0), "=r"(r1), "=r"(r2), "=r"(r3) : "r"(a));
}
__device__ __forceinline__ void ldsm4t(uint32_t& r0, uint32_t& r1,
                                       uint32_t& r2, uint32_t& r3, uint32_t a) {
    asm volatile("ldmatrix.sync.aligned.m8n8.x4.trans.shared.b16 {%0,%1,%2,%3}, [%4];"
                 : "=r"(r0), "=r"(r1), "=r"(r2), "=r"(r3) : "r"(a));
}
#define MMA_F16(d, a, b) asm volatile( \
    "mma.sync.aligned.m16n8k16.row.col.f32.f16.f16.f32 " \
    "{%0,%1,%2,%3}, {%4,%5,%6,%7}, {%8,%9}, {%0,%1,%2,%3};\n" \
    : "+f"(d[0]), "+f"(d[1]), "+f"(d[2]), "+f"(d[3]) \
    : "r"(a[0]), "r"(a[1]), "r"(a[2]), "r"(a[3]), "r"(b[0]), "r"(b[1]))

#define MMA_S(d, a0, a1, a2, a3, b0, b1) asm volatile( \
    "mma.sync.aligned.m16n8k16.row.col.f32.f16.f16.f32 " \
    "{%0,%1,%2,%3}, {%4,%5,%6,%7}, {%8,%9}, {%0,%1,%2,%3};\n" \
    : "+f"(d[0]), "+f"(d[1]), "+f"(d[2]), "+f"(d[3]) \
    : "r"(a0), "r"(a1), "r"(a2), "r"(a3), "r"(b0), "r"(b1))

__device__ __forceinline__ void split2(float x, float y, uint32_t& hi, uint32_t& lo) {
    __half2 h = __floats2half2_rn(x, y);
    float2 hf = __half22float2(h);
    __half2 l = __floats2half2_rn(x - hf.x, y - hf.y);
    hi = *(uint32_t*)&h;
    lo = *(uint32_t*)&l;
}
__device__ __forceinline__ uint32_t pk2(float x, float y) {
    __half2 h = __floats2half2_rn(x, y);
    return *(uint32_t*)&h;
}

// ---------------- fp32 -> fp16 convert (contiguous) --------------------------
__global__ __launch_bounds__(256) void conv_f16(
    const float4* __restrict__ src, uint2* __restrict__ dst, int n4)
{
    int i = blockIdx.x * blockDim.x + threadIdx.x;
    if (i >= n4) return;
    float4 v = src[i];
    __half2 h01 = __floats2half2_rn(v.x, v.y);
    __half2 h23 = __floats2half2_rn(v.z, v.w);
    uint2 o;
    o.x = *(const uint32_t*)&h01;
    o.y = *(const uint32_t*)&h23;
    dst[i] = o;
}

// ---------------- fp32 W[K][N] -> fp16 transposed [N][K], 3 weights ----------
__global__ __launch_bounds__(256) void convT_w3(
    const float* __restrict__ W0, const float* __restrict__ W1,
    const float* __restrict__ W2, __half* __restrict__ T)
{
    __shared__ float tile[32][33];
    const float* W = (blockIdx.z == 0) ? W0 : (blockIdx.z == 1) ? W1 : W2;
    __half* Tz = T + (size_t)blockIdx.z * GK * GN;
    const int tx = threadIdx.x & 31, ty = threadIdx.x >> 5;
    const int k0 = blockIdx.y * 32, n0 = blockIdx.x * 32;
#pragma unroll
    for (int r = 0; r < 4; r++)
        tile[ty + r * 8][tx] = W[(size_t)(k0 + ty + r * 8) * GN + n0 + tx];
    __syncthreads();
#pragma unroll
    for (int r = 0; r < 4; r++) {
        size_t o = (size_t)(n0 + ty + r * 8) * GK + k0 + tx;
        Tz[o] = __float2half(tile[tx][ty + r * 8]);
    }
}

__global__ __launch_bounds__(256) void convT_w(
    const float* __restrict__ W, __half* __restrict__ T)
{
    __shared__ float tile[32][33];
    const int tx = threadIdx.x & 31, ty = threadIdx.x >> 5;
    const int k0 = blockIdx.y * 32, n0 = blockIdx.x * 32;
#pragma unroll
    for (int r = 0; r < 4; r++)
        tile[ty + r * 8][tx] = W[(size_t)(k0 + ty + r * 8) * GN + n0 + tx];
    __syncthreads();
#pragma unroll
    for (int r = 0; r < 4; r++) {
        size_t o = (size_t)(n0 + ty + r * 8) * GK + k0 + tx;
        T[o] = __float2half(tile[tx][ty + r * 8]);
    }
}

// ---------------- fp16 GEMM on mma.sync (HMMA) -------------------------------
// CTA tile 128x64, BK=32, 4-stage cp.async, 4 CTAs/SM.
// Unswizzled conflict-free layout: chunk (row r, k-quarter h) at
//   ((r>>3)*4 + h)*128 + (r&7)*16  — every ldsm wavefront = one 128B line.
#define STG_BYTES 12288                  // A 8KB + B 4KB
#define B_OFF 8192
#define SMEM_DYN (4 * STG_BYTES)         // 49152
#define NITER (GK / 32)                  // 32

template <int OUT_HALF>
__global__ __launch_bounds__(256, 4) void gemm_f16(
    const __half* __restrict__ A, const __half* __restrict__ B,
    const float* __restrict__ bias, void* __restrict__ Cv, int ldc)
{
    extern __shared__ __align__(1024) char smem[];
    const uint32_t sb = smem_u32(smem);
    const int tid  = threadIdx.x;
    const int lane = tid & 31;
    const int wid  = tid >> 5;
    const int wm   = wid & 3;        // 4 warps along M (32 rows each)
    const int wn   = wid >> 2;       // 2 warps along N (32 cols each)
    const int brow = blockIdx.y * 128;
    const int bcol = blockIdx.x * 64;

    // ---- fill geometry (BK=32): A 512 chunks (2/thread), B 256 (1/thread)
    const __half* pA0;
    const __half* pA1;
    const __half* pB0;
    uint32_t sA0, sA1, sB0;
    {
        int c = tid;                      // A chunk 0
        int r = c >> 2, h = c & 3;
        sA0 = (uint32_t)(((r >> 3) * 4 + h) * 128 + (r & 7) * 16);
        pA0 = A + (size_t)(brow + r) * GK + h * 8;
        c = tid + 256;                    // A chunk 1
        r = c >> 2; h = c & 3;
        sA1 = (uint32_t)(((r >> 3) * 4 + h) * 128 + (r & 7) * 16);
        pA1 = A + (size_t)(brow + r) * GK + h * 8;
        c = tid;                          // B chunk
        int n = c >> 2; h = c & 3;
        sB0 = (uint32_t)(B_OFF + ((n >> 3) * 4 + h) * 128 + (n & 7) * 16);
        pB0 = B + (size_t)(bcol + n) * GK + h * 8;
    }

#define FILL(stg, k0)                                                        \
    do {                                                                     \
        const uint32_t so_ = sb + (uint32_t)(stg) * STG_BYTES;               \
        cp16(so_ + sA0, pA0 + (k0));                                         \
        cp16(so_ + sA1, pA1 + (k0));                                         \
        cp16(so_ + sB0, pB0 + (k0));                                         \
        asm volatile("cp.async.commit_group;" ::: "memory");                 \
    } while (0)

    // ---- fragment geometry (line index precomputed; +h*128 at use site)
    const uint32_t a_kc = ((lane >> 4) & 1) * 128;
    const uint32_t b_kc = ((lane >> 3) & 1) * 128;
    uint32_t aline[2], bline[2];
#pragma unroll
    for (int mt = 0; mt < 2; mt++)
        aline[mt] = (uint32_t)((wm * 4 + mt * 2 + ((lane >> 3) & 1)) * 512
                               + (lane & 7) * 16);
#pragma unroll
    for (int np = 0; np < 2; np++)
        bline[np] = (uint32_t)(B_OFF
                               + (wn * 4 + np * 2 + ((lane >> 4) & 1)) * 512
                               + (lane & 7) * 16);

    float acc[2][4][4];
#pragma unroll
    for (int mt = 0; mt < 2; mt++)
#pragma unroll
        for (int nt = 0; nt < 4; nt++)
#pragma unroll
            for (int q = 0; q < 4; q++) acc[mt][nt][q] = 0.f;

    // ---- prologue: 3 stages in flight
    FILL(0, 0);
    FILL(1, 32);
    FILL(2, 64);

    for (int s = 0; s < NITER; s++) {
        if (s < NITER - 2)       asm volatile("cp.async.wait_group 2;" ::: "memory");
        else if (s == NITER - 2) asm volatile("cp.async.wait_group 1;" ::: "memory");
        else                     asm volatile("cp.async.wait_group 0;" ::: "memory");
        __syncthreads();

        if (s + 3 < NITER) FILL((s + 3) & 3, (s + 3) * 32);

        const uint32_t stg = sb + (uint32_t)(s & 3) * STG_BYTES;
#pragma unroll
        for (int kk = 0; kk < 2; kk++) {
            uint32_t a[2][4];
#pragma unroll
            for (int mt = 0; mt < 2; mt++) {
                const uint32_t ad = stg + aline[mt]
                    + (uint32_t)(kk * 256) + a_kc;
                ldsm4(a[mt][0], a[mt][1], a[mt][2], a[mt][3], ad);
            }
            uint32_t b[4][2];
#pragma unroll
            for (int np = 0; np < 2; np++) {
                const uint32_t bd = stg + bline[np]
                    + (uint32_t)(kk * 256) + b_kc;
                ldsm4(b[2 * np][0], b[2 * np][1],
                      b[2 * np + 1][0], b[2 * np + 1][1], bd);
            }
#pragma unroll
            for (int mt = 0; mt < 2; mt++)
#pragma unroll
                for (int nt = 0; nt < 4; nt++)
                    MMA_F16(acc[mt][nt], a[mt], b[nt]);
        }
    }

#pragma unroll
    for (int mt = 0; mt < 2; mt++) {
        const int row = brow + wm * 32 + mt * 16 + (lane >> 2);
#pragma unroll
        for (int nt = 0; nt < 4; nt++) {
            const int col = bcol + wn * 32 + nt * 8 + (lane & 3) * 2;
            const float b0 = __ldg(bias + col), b1 = __ldg(bias + col + 1);
            if (OUT_HALF) {
                __half* C = (__half*)Cv;
                __half2 p0 = __floats2half2_rn(acc[mt][nt][0] + b0,
                                               acc[mt][nt][1] + b1);
                __half2 p1 = __floats2half2_rn(acc[mt][nt][2] + b0,
                                               acc[mt][nt][3] + b1);
                *(uint32_t*)&C[(size_t)row * ldc + col] = *(uint32_t*)&p0;
                *(uint32_t*)&C[(size_t)(row + 8) * ldc + col] = *(uint32_t*)&p1;
            } else {
                float* C = (float*)Cv;
                float2 o;
                o.x = acc[mt][nt][0] + b0;
                o.y = acc[mt][nt][1] + b1;
                *(float2*)&C[(size_t)row * ldc + col] = o;
                o.x = acc[mt][nt][2] + b0;
                o.y = acc[mt][nt][3] + b1;
                *(float2*)&C[(size_t)(row + 8) * ldc + col] = o;
            }
        }
    }
}

// ---------------- per-(b,h) irrep attention: tensor-core (R12/13, validated) --
#define PA_H  0
#define PA_L  8192
#define PB_H  16384
#define QKV_O 24576
#define HEADB 6912
#define SS_O  (QKV_O + 8 * HEADB)      // 79872
#define AT_SMEM (SS_O + 8 * 1088)      // 88576
#define QP    72                        // halves per row (144B pitch)

__global__ __launch_bounds__(256) void psead_attn(
    const __half* __restrict__ QKV, const float* __restrict__ proj,
    __half* __restrict__ Tg)
{
    extern __shared__ __align__(16) char sm[];
    const uint32_t sb = smem_u32(sm);
    const int tid  = threadIdx.x;
    const int wid  = tid >> 5;
    const int lane = tid & 31;
    const int g    = lane >> 2;
    const int tg   = lane & 3;

    // ---- P fragment prep (block-wide)
    for (int s = tid; s < NIRR * 32; s += 256) {
        const int p = s >> 5, ln = s & 31;
        const int gg = ln >> 2, tt = ln & 3;
        const float* Pp = proj + p * 256;
        float a0x = Pp[gg * 16 + 2 * tt],       a0y = Pp[gg * 16 + 2 * tt + 1];
        float a1x = Pp[(gg + 8) * 16 + 2 * tt], a1y = Pp[(gg + 8) * 16 + 2 * tt + 1];
        float a2x = Pp[gg * 16 + 2 * tt + 8],   a2y = Pp[gg * 16 + 2 * tt + 9];
        float a3x = Pp[(gg + 8) * 16 + 2 * tt + 8], a3y = Pp[(gg + 8) * 16 + 2 * tt + 9];
        uint4 ph, pl;
        split2(a0x, a0y, ph.x, pl.x);
        split2(a1x, a1y, ph.y, pl.y);
        split2(a2x, a2y, ph.z, pl.z);
        split2(a3x, a3y, ph.w, pl.w);
        ((uint4*)(sm + PA_H))[p * 32 + ln] = ph;
        ((uint4*)(sm + PA_L))[p * 32 + ln] = pl;
        uint4 pb;
        pb.x = pk2(Pp[(2 * tt) * 16 + gg],     Pp[(2 * tt + 1) * 16 + gg]);
        pb.y = pk2(Pp[(2 * tt + 8) * 16 + gg], Pp[(2 * tt + 9) * 16 + gg]);
        pb.z = pk2(Pp[(2 * tt) * 16 + gg + 8],     Pp[(2 * tt + 1) * 16 + gg + 8]);
        pb.w = pk2(Pp[(2 * tt + 8) * 16 + gg + 8], Pp[(2 * tt + 9) * 16 + gg + 8]);
        ((uint4*)(sm + PB_H))[p * 32 + ln] = pb;
    }

    // ---- per-head q/k/v loads (merged buffer, pitch N3)
    const int ghead = blockIdx.x * 8 + wid;
    const int b = ghead >> 4, h = ghead & 15;
    const size_t baseq = (size_t)(b * K_SEQ) * N3 + (size_t)h * HD;
    const size_t baset = (size_t)b * (K_SEQ * D_DIM) + (size_t)h * HD;
    const uint32_t SQ = QKV_O + wid * HEADB;
    const uint32_t SK = SQ + 16 * QP * 2;
    const uint32_t SV = SK + 16 * QP * 2;
#pragma unroll
    for (int t = 0; t < 4; t++) {
        const int c = lane + t * 32;
        const int row = c >> 3, cw = c & 7;
        const uint32_t so = row * (QP * 2) + cw * 16;
        const size_t go = baseq + (size_t)row * N3 + cw * 8;
        *(uint4*)(sm + SQ + so) = *(const uint4*)(QKV + go);
        *(uint4*)(sm + SK + so) = *(const uint4*)(QKV + go + GN);
        *(uint4*)(sm + SV + so) = *(const uint4*)(QKV + go + 2 * GN);
    }
    __syncthreads();

    const uint32_t lrow = (uint32_t)(lane & 15) * (QP * 2);
    const uint32_t lcol8 = (uint32_t)((lane >> 4) * 8) * 2;

    // ---- S = (1/8) Q K^T
    float S0[4] = {0.f, 0.f, 0.f, 0.f};
    float S1[4] = {0.f, 0.f, 0.f, 0.f};
#pragma unroll
    for (int kc = 0; kc < 4; kc++) {
        uint32_t qa0, qa1, qa2, qa3;
        ldsm4(qa0, qa1, qa2, qa3, sb + SQ + lrow + (uint32_t)(kc * 32) + lcol8);
        uint32_t kb0, kb1, kb2, kb3;
        ldsm4(kb0, kb1, kb2, kb3, sb + SK + lrow + (uint32_t)(kc * 32) + lcol8);
        MMA_S(S0, qa0, qa1, qa2, qa3, kb0, kb2);
        MMA_S(S1, qa0, qa1, qa2, qa3, kb1, kb3);
    }
    float* sS = (float*)(sm + SS_O + wid * 1088);
    sS[g * 17 + 2 * tg]             = S0[0] * 0.125f;
    sS[g * 17 + 2 * tg + 1]         = S0[1] * 0.125f;
    sS[(g + 8) * 17 + 2 * tg]       = S0[2] * 0.125f;
    sS[(g + 8) * 17 + 2 * tg + 1]   = S0[3] * 0.125f;
    sS[g * 17 + 2 * tg + 8]         = S1[0] * 0.125f;
    sS[g * 17 + 2 * tg + 9]         = S1[1] * 0.125f;
    sS[(g + 8) * 17 + 2 * tg + 8]   = S1[2] * 0.125f;
    sS[(g + 8) * 17 + 2 * tg + 9]   = S1[3] * 0.125f;
    __syncwarp();

    uint32_t sh[4], sl[4];
    {
        float x0 = sS[(2 * tg) * 17 + g],     x1 = sS[(2 * tg + 1) * 17 + g];
        float x2 = sS[(2 * tg + 8) * 17 + g], x3 = sS[(2 * tg + 9) * 17 + g];
        float y0 = sS[(2 * tg) * 17 + g + 8],     y1 = sS[(2 * tg + 1) * 17 + g + 8];
        float y2 = sS[(2 * tg + 8) * 17 + g + 8], y3 = sS[(2 * tg + 9) * 17 + g + 8];
        split2(x0, x1, sh[0], sl[0]);
        split2(x2, x3, sh[1], sl[1]);
        split2(y0, y1, sh[2], sl[2]);
        split2(y2, y3, sh[3], sl[3]);
    }

    // ---- irrep loop
    const uint4* paH = (const uint4*)(sm + PA_H);
    const uint4* paL = (const uint4*)(sm + PA_L);
    const uint4* pbH = (const uint4*)(sm + PB_H);
    float M0[4] = {0.f, 0.f, 0.f, 0.f};
    float M1[4] = {0.f, 0.f, 0.f, 0.f};
    for (int p = 0; p < NIRR; p++) {
        const uint4 ph = paH[p * 32 + lane];
        const uint4 pl = paL[p * 32 + lane];
        const uint4 pb = pbH[p * 32 + lane];

        float T0[4] = {0.f, 0.f, 0.f, 0.f};
        float T1[4] = {0.f, 0.f, 0.f, 0.f};
        MMA_S(T0, ph.x, ph.y, ph.z, ph.w, sh[0], sh[1]);
        MMA_S(T1, ph.x, ph.y, ph.z, ph.w, sh[2], sh[3]);
        MMA_S(T0, ph.x, ph.y, ph.z, ph.w, sl[0], sl[1]);
        MMA_S(T1, ph.x, ph.y, ph.z, ph.w, sl[2], sl[3]);
        MMA_S(T0, pl.x, pl.y, pl.z, pl.w, sh[0], sh[1]);
        MMA_S(T1, pl.x, pl.y, pl.z, pl.w, sh[2], sh[3]);

        uint32_t tH[4], tL[4];
        split2(T0[0], T0[1], tH[0], tL[0]);
        split2(T0[2], T0[3], tH[1], tL[1]);
        split2(T1[0], T1[1], tH[2], tL[2]);
        split2(T1[2], T1[3], tH[3], tL[3]);

        float z0[4] = {0.f, 0.f, 0.f, 0.f};
        float z1[4] = {0.f, 0.f, 0.f, 0.f};
        MMA_S(z0, tH[0], tH[1], tH[2], tH[3], ph.x, ph.z);
        MMA_S(z1, tH[0], tH[1], tH[2], tH[3], ph.y, ph.w);
        MMA_S(z0, tH[0], tH[1], tH[2], tH[3], pl.x, pl.z);
        MMA_S(z1, tH[0], tH[1], tH[2], tH[3], pl.y, pl.w);
        MMA_S(z0, tL[0], tL[1], tL[2], tL[3], ph.x, ph.z);
        MMA_S(z1, tL[0], tL[1], tL[2], tL[3], ph.y, ph.w);

        const float e00 = __expf(z0[0]), e01 = __expf(z0[1]);
        const float e10 = __expf(z1[0]), e11 = __expf(z1[1]);
        const float e02 = __expf(z0[2]), e03 = __expf(z0[3]);
        const float e12 = __expf(z1[2]), e13 = __expf(z1[3]);
        float sg = e00 + e01 + e10 + e11;
        float s8 = e02 + e03 + e12 + e13;
        sg += __shfl_xor_sync(0xffffffffu, sg, 1);
        sg += __shfl_xor_sync(0xffffffffu, sg, 2);
        s8 += __shfl_xor_sync(0xffffffffu, s8, 1);
        s8 += __shfl_xor_sync(0xffffffffu, s8, 2);
        const float i0 = __frcp_rn(sg), i1 = __frcp_rn(s8);

        uint32_t w0 = pk2(e00 * i0, e01 * i0);
        uint32_t w1 = pk2(e02 * i1, e03 * i1);
        uint32_t w2 = pk2(e10 * i0, e11 * i0);
        uint32_t w3 = pk2(e12 * i1, e13 * i1);

        MMA_S(M0, w0, w1, w2, w3, pb.x, pb.y);
        MMA_S(M1, w0, w1, w2, w3, pb.z, pb.w);
    }

    // ---- out = M * V
    uint32_t mf0 = pk2(M0[0], M0[1]);
    uint32_t mf1 = pk2(M0[2], M0[3]);
    uint32_t mf2 = pk2(M1[0], M1[1]);
    uint32_t mf3 = pk2(M1[2], M1[3]);
#pragma unroll
    for (int nc = 0; nc < 4; nc++) {
        uint32_t vb0, vb1, vb2, vb3;
        ldsm4t(vb0, vb1, vb2, vb3, sb + SV + lrow + (uint32_t)(nc * 32) + lcol8);
        float OA[4] = {0.f, 0.f, 0.f, 0.f};
        float OB[4] = {0.f, 0.f, 0.f, 0.f};
        MMA_S(OA, mf0, mf1, mf2, mf3, vb0, vb1);
        MMA_S(OB, mf0, mf1, mf2, mf3, vb2, vb3);
        __half* dst = Tg + baset;
        const int c0 = nc * 16 + 2 * tg;
        *(uint32_t*)(dst + (size_t)g * D_DIM + c0)           = pk2(OA[0], OA[1]);
        *(uint32_t*)(dst + (size_t)g * D_DIM + c0 + 8)       = pk2(OB[0], OB[1]);
        *(uint32_t*)(dst + (size_t)(g + 8) * D_DIM + c0)     = pk2(OA[2], OA[3]);
        *(uint32_t*)(dst + (size_t)(g + 8) * D_DIM + c0 + 8) = pk2(OB[2], OB[3]);
    }
}

// ---------------- launch -----------------------------------------------------
extern "C" void kernel_launch(void* const* d_in, const int* in_sizes, int n_in,
                              void* d_out, int out_size)
{
    (void)in_sizes; (void)n_in; (void)out_size;
    const float* x    = (const float*)d_in[0];
    const float* proj = (const float*)d_in[1];
    const float* Wq   = (const float*)d_in[2];
    const float* bq   = (const float*)d_in[3];
    const float* Wk   = (const float*)d_in[4];
    const float* bk   = (const float*)d_in[5];
    const float* Wv   = (const float*)d_in[6];
    const float* bv   = (const float*)d_in[7];
    const float* Wo   = (const float*)d_in[8];
    const float* bo   = (const float*)d_in[9];
    float* out = (float*)d_out;

    __half *xh, *qkv, *th, *wt;
    float* gb;
    cudaGetSymbolAddress((void**)&xh, g_xh);
    cudaGetSymbolAddress((void**)&qkv, g_qkv);
    cudaGetSymbolAddress((void**)&th, g_th);
    cudaGetSymbolAddress((void**)&wt, g_wt);
    cudaGetSymbolAddress((void**)&gb, g_bias);

    cudaFuncSetAttribute(gemm_f16<1>, cudaFuncAttributeMaxDynamicSharedMemorySize,
                         SMEM_DYN);
    cudaFuncSetAttribute(gemm_f16<0>, cudaFuncAttributeMaxDynamicSharedMemorySize,
                         SMEM_DYN);
    cudaFuncSetAttribute(psead_attn, cudaFuncAttributeMaxDynamicSharedMemorySize,
                         AT_SMEM);

    const int WSZ = GK * GN;
    const int n4 = GM * GK / 4;

    // bias concat (graph-capturable async D2D copies)
    cudaMemcpyAsync(gb,        bq, GN * sizeof(float), cudaMemcpyDeviceToDevice);
    cudaMemcpyAsync(gb + GN,   bk, GN * sizeof(float), cudaMemcpyDeviceToDevice);
    cudaMemcpyAsync(gb + 2*GN, bv, GN * sizeof(float), cudaMemcpyDeviceToDevice);

    conv_f16<<<(n4 + 255) / 256, 256>>>((const float4*)x, (uint2*)xh, n4);   // k0
    {
        dim3 tg3(GN / 32, GK / 32, 3);
        convT_w3<<<tg3, 256>>>(Wq, Wk, Wv, wt);                              // k1
    }
    {
        dim3 tg(GN / 32, GK / 32);
        convT_w<<<tg, 256>>>(Wo, wt + 3 * WSZ);                              // k2
    }
    {
        dim3 gg(N3 / 64, GM / 128);   // (48, 128) merged QKV
        gemm_f16<1><<<gg, 256, SMEM_DYN>>>(xh, wt, gb, qkv, N3);             // k3 (ncu slot)
    }
    psead_attn<<<B_SZ * H_NUM / 8, 256, AT_SMEM>>>(qkv, proj, th);           // k4
    {
        dim3 gg(GN / 64, GM / 128);   // (16, 128)
        gemm_f16<0><<<gg, 256, SMEM_DYN>>>(th, wt + 3 * WSZ, bo, out, GN);   // k5
    }
}

// round 15
// speedup vs baseline: 1.9305x; 1.9305x over previous
#include <cuda_runtime.h>
#include <cuda_fp16.h>
#include <cstdint>

// Problem constants
#define B_SZ    1024
#define K_SEQ   16
#define D_DIM   1024
#define H_NUM   16
#define HD      64
#define NIRR    16

#define GM      (B_SZ * K_SEQ)   // 16384
#define GN      D_DIM            // 1024
#define GK      D_DIM            // 1024
#define N3      (3 * GN)         // 3072

// ---------------- scratch (device globals: no allocations allowed) ----------
__device__ __half g_xh[GM * GK];
__device__ __half g_qkv[(size_t)GM * N3];   // merged Q|K|V, pitch 3072
__device__ __half g_th[GM * GN];
__device__ __half g_wt[4][GK * GN];         // transposed weights [N][K], fp16
__device__ float  g_bias[N3];               // concat bq|bk|bv

// ---------------- helpers -----------------------------------------------------
__device__ __forceinline__ uint32_t smem_u32(const void* p) {
    uint32_t a;
    asm("{ .reg .u64 t; cvta.to.shared.u64 t, %1; cvt.u32.u64 %0, t; }"
        : "=r"(a) : "l"(p));
    return a;
}
__device__ __forceinline__ void cp16(uint32_t daddr, const void* g) {
    asm volatile("cp.async.cg.shared.global [%0], [%1], 16;\n"
                 :: "r"(daddr), "l"(g) : "memory");
}
__device__ __forceinline__ void ldsm4(uint32_t& r0, uint32_t& r1,
                                      uint32_t& r2, uint32_t& r3, uint32_t a) {
    asm volatile("ldmatrix.sync.aligned.m8n8.x4.shared.b16 {%0,%1,%2,%3}, [%4];"
                 : "=r"(r0), "=r"(r1), "=r"(r2), "=r"(r3) : "r"(a));
}
__device__ __forceinline__ void ldsm4t(uint32_t& r0, uint32_t& r1,
                                       uint32_t& r2, uint32_t& r3, uint32_t a) {
    asm volatile("ldmatrix.sync.aligned.m8n8.x4.trans.shared.b16 {%0,%1,%2,%3}, [%4];"
                 : "=r"(r0), "=r"(r1), "=r"(r2), "=r"(r3) : "r"(a));
}
#define MMA_F16(d, a, b) asm volatile( \
    "mma.sync.aligned.m16n8k16.row.col.f32.f16.f16.f32 " \
    "{%0,%1,%2,%3}, {%4,%5,%6,%7}, {%8,%9}, {%0,%1,%2,%3};\n" \
    : "+f"(d[0]), "+f"(d[1]), "+f"(d[2]), "+f"(d[3]) \
    : "r"(a[0]), "r"(a[1]), "r"(a[2]), "r"(a[3]), "r"(b[0]), "r"(b[1]))

#define MMA_S(d, a0, a1, a2, a3, b0, b1) asm volatile( \
    "mma.sync.aligned.m16n8k16.row.col.f32.f16.f16.f32 " \
    "{%0,%1,%2,%3}, {%4,%5,%6,%7}, {%8,%9}, {%0,%1,%2,%3};\n" \
    : "+f"(d[0]), "+f"(d[1]), "+f"(d[2]), "+f"(d[3]) \
    : "r"(a0), "r"(a1), "r"(a2), "r"(a3), "r"(b0), "r"(b1))

__device__ __forceinline__ void split2(float x, float y, uint32_t& hi, uint32_t& lo) {
    __half2 h = __floats2half2_rn(x, y);
    float2 hf = __half22float2(h);
    __half2 l = __floats2half2_rn(x - hf.x, y - hf.y);
    hi = *(uint32_t*)&h;
    lo = *(uint32_t*)&l;
}
__device__ __forceinline__ uint32_t pk2(float x, float y) {
    __half2 h = __floats2half2_rn(x, y);
    return *(uint32_t*)&h;
}

// ---------------- fp32 -> fp16 convert (contiguous) --------------------------
__global__ __launch_bounds__(256) void conv_f16(
    const float4* __restrict__ src, uint2* __restrict__ dst, int n4)
{
    int i = blockIdx.x * blockDim.x + threadIdx.x;
    if (i >= n4) return;
    float4 v = src[i];
    __half2 h01 = __floats2half2_rn(v.x, v.y);
    __half2 h23 = __floats2half2_rn(v.z, v.w);
    uint2 o;
    o.x = *(const uint32_t*)&h01;
    o.y = *(const uint32_t*)&h23;
    dst[i] = o;
}

// ---------------- fp32 W[K][N] -> fp16 transposed [N][K], 4 weights ----------
__global__ __launch_bounds__(256) void convT_w4(
    const float* __restrict__ W0, const float* __restrict__ W1,
    const float* __restrict__ W2, const float* __restrict__ W3,
    __half* __restrict__ T)
{
    __shared__ float tile[32][33];
    const float* W = (blockIdx.z == 0) ? W0 : (blockIdx.z == 1) ? W1
                   : (blockIdx.z == 2) ? W2 : W3;
    __half* Tz = T + (size_t)blockIdx.z * GK * GN;
    const int tx = threadIdx.x & 31, ty = threadIdx.x >> 5;
    const int k0 = blockIdx.y * 32, n0 = blockIdx.x * 32;
#pragma unroll
    for (int r = 0; r < 4; r++)
        tile[ty + r * 8][tx] = W[(size_t)(k0 + ty + r * 8) * GN + n0 + tx];
    __syncthreads();
#pragma unroll
    for (int r = 0; r < 4; r++) {
        size_t o = (size_t)(n0 + ty + r * 8) * GK + k0 + tx;
        Tz[o] = __float2half(tile[tx][ty + r * 8]);
    }
}

// ---------------- fp16 GEMM on mma.sync (HMMA) — R13 config, validated -------
// CTA tile 128x64, BK=64, 2-stage cp.async, 4 CTAs/SM (64 regs).
#define STG_BYTES 24576
#define SMEM_DYN (2 * STG_BYTES)        // 49152
#define NITER (GK / 64)                 // 16

template <int OUT_HALF>
__global__ __launch_bounds__(256, 4) void gemm_f16(
    const __half* __restrict__ A, const __half* __restrict__ B,
    const float* __restrict__ bias, void* __restrict__ Cv, int ldc)
{
    extern __shared__ __align__(1024) char smem[];
    const uint32_t sb = smem_u32(smem);
    const int tid  = threadIdx.x;
    const int lane = tid & 31;
    const int wid  = tid >> 5;
    const int wm   = wid & 3;
    const int wn   = wid >> 2;
    const int brow = blockIdx.y * 128;
    const int bcol = blockIdx.x * 64;

    const __half* pA[4];
    uint32_t sA[4];
#pragma unroll
    for (int t = 0; t < 4; t++) {
        const int c = tid + t * 256;
        const int row = c >> 3, cw = c & 7;
        sA[t] = (uint32_t)(row * 128 + ((cw ^ (row & 7)) << 4));
        pA[t] = A + (size_t)(brow + row) * GK + cw * 8;
    }
    const __half* pB[2];
    uint32_t sB[2];
#pragma unroll
    for (int t = 0; t < 2; t++) {
        const int c = tid + t * 256;
        const int row = c >> 3, cw = c & 7;
        sB[t] = (uint32_t)(16384 + row * 128 + ((cw ^ (row & 7)) << 4));
        pB[t] = B + (size_t)(bcol + row) * GK + cw * 8;
    }

#define FILL(stg, k0)                                                        \
    do {                                                                     \
        const uint32_t so_ = sb + (uint32_t)(stg) * STG_BYTES;               \
        _Pragma("unroll")                                                    \
        for (int t_ = 0; t_ < 4; t_++) cp16(so_ + sA[t_], pA[t_] + (k0));    \
        _Pragma("unroll")                                                    \
        for (int t_ = 0; t_ < 2; t_++) cp16(so_ + sB[t_], pB[t_] + (k0));    \
        asm volatile("cp.async.commit_group;" ::: "memory");                 \
    } while (0)

    const int lsw  = lane & 7;
    const int a_kc = (lane >> 4) & 1;
    const int b_kc = (lane >> 3) & 1;
    uint32_t a_ro[2], b_ro[2];
#pragma unroll
    for (int mt = 0; mt < 2; mt++)
        a_ro[mt] = (uint32_t)(wm * 32 + mt * 16 + (lane & 7) + ((lane >> 3) & 1) * 8) * 128;
#pragma unroll
    for (int np = 0; np < 2; np++)
        b_ro[np] = (uint32_t)(wn * 32 + np * 16 + (lane & 7) + ((lane >> 4) & 1) * 8) * 128
                   + 16384;

    float acc[2][4][4];
#pragma unroll
    for (int mt = 0; mt < 2; mt++)
#pragma unroll
        for (int nt = 0; nt < 4; nt++)
#pragma unroll
            for (int q = 0; q < 4; q++) acc[mt][nt][q] = 0.f;

    FILL(0, 0);
    FILL(1, 64);

    for (int s = 0; s < NITER; s++) {
        if (s == NITER - 1) asm volatile("cp.async.wait_group 0;" ::: "memory");
        else                asm volatile("cp.async.wait_group 1;" ::: "memory");
        __syncthreads();

        const uint32_t stg = sb + (uint32_t)(s & 1) * STG_BYTES;
#pragma unroll
        for (int kk = 0; kk < 4; kk++) {
            uint32_t a[2][4];
#pragma unroll
            for (int mt = 0; mt < 2; mt++) {
                const uint32_t ad = stg + a_ro[mt]
                    + ((uint32_t)((kk * 2 + a_kc) ^ lsw) << 4);
                ldsm4(a[mt][0], a[mt][1], a[mt][2], a[mt][3], ad);
            }
            uint32_t b[4][2];
#pragma unroll
            for (int np = 0; np < 2; np++) {
                const uint32_t bd = stg + b_ro[np]
                    + ((uint32_t)((kk * 2 + b_kc) ^ lsw) << 4);
                ldsm4(b[2 * np][0], b[2 * np][1],
                      b[2 * np + 1][0], b[2 * np + 1][1], bd);
            }
#pragma unroll
            for (int mt = 0; mt < 2; mt++)
#pragma unroll
                for (int nt = 0; nt < 4; nt++)
                    MMA_F16(acc[mt][nt], a[mt], b[nt]);
        }

        if (s + 2 < NITER) {
            __syncthreads();          // all reads of this slot done
            FILL(s & 1, (s + 2) * 64);
        }
    }

#pragma unroll
    for (int mt = 0; mt < 2; mt++) {
        const int row = brow + wm * 32 + mt * 16 + (lane >> 2);
#pragma unroll
        for (int nt = 0; nt < 4; nt++) {
            const int col = bcol + wn * 32 + nt * 8 + (lane & 3) * 2;
            const float b0 = __ldg(bias + col), b1 = __ldg(bias + col + 1);
            if (OUT_HALF) {
                __half* C = (__half*)Cv;
                __half2 p0 = __floats2half2_rn(acc[mt][nt][0] + b0,
                                               acc[mt][nt][1] + b1);
                __half2 p1 = __floats2half2_rn(acc[mt][nt][2] + b0,
                                               acc[mt][nt][3] + b1);
                *(uint32_t*)&C[(size_t)row * ldc + col] = *(uint32_t*)&p0;
                *(uint32_t*)&C[(size_t)(row + 8) * ldc + col] = *(uint32_t*)&p1;
            } else {
                float* C = (float*)Cv;
                float2 o;
                o.x = acc[mt][nt][0] + b0;
                o.y = acc[mt][nt][1] + b1;
                *(float2*)&C[(size_t)row * ldc + col] = o;
                o.x = acc[mt][nt][2] + b0;
                o.y = acc[mt][nt][3] + b1;
                *(float2*)&C[(size_t)(row + 8) * ldc + col] = o;
            }
        }
    }
}

// ---------------- per-(b,h) irrep attention: tensor-core (R12/13, validated) --
#define PA_H  0
#define PA_L  8192
#define PB_H  16384
#define QKV_O 24576
#define HEADB 6912
#define SS_O  (QKV_O + 8 * HEADB)      // 79872
#define AT_SMEM (SS_O + 8 * 1088)      // 88576
#define QP    72                        // halves per row (144B pitch)

__global__ __launch_bounds__(256) void psead_attn(
    const __half* __restrict__ QKV, const float* __restrict__ proj,
    __half* __restrict__ Tg)
{
    extern __shared__ __align__(16) char sm[];
    const uint32_t sb = smem_u32(sm);
    const int tid  = threadIdx.x;
    const int wid  = tid >> 5;
    const int lane = tid & 31;
    const int g    = lane >> 2;
    const int tg   = lane & 3;

    // ---- P fragment prep (block-wide)
    for (int s = tid; s < NIRR * 32; s += 256) {
        const int p = s >> 5, ln = s & 31;
        const int gg = ln >> 2, tt = ln & 3;
        const float* Pp = proj + p * 256;
        float a0x = Pp[gg * 16 + 2 * tt],       a0y = Pp[gg * 16 + 2 * tt + 1];
        float a1x = Pp[(gg + 8) * 16 + 2 * tt], a1y = Pp[(gg + 8) * 16 + 2 * tt + 1];
        float a2x = Pp[gg * 16 + 2 * tt + 8],   a2y = Pp[gg * 16 + 2 * tt + 9];
        float a3x = Pp[(gg + 8) * 16 + 2 * tt + 8], a3y = Pp[(gg + 8) * 16 + 2 * tt + 9];
        uint4 ph, pl;
        split2(a0x, a0y, ph.x, pl.x);
        split2(a1x, a1y, ph.y, pl.y);
        split2(a2x, a2y, ph.z, pl.z);
        split2(a3x, a3y, ph.w, pl.w);
        ((uint4*)(sm + PA_H))[p * 32 + ln] = ph;
        ((uint4*)(sm + PA_L))[p * 32 + ln] = pl;
        uint4 pb;
        pb.x = pk2(Pp[(2 * tt) * 16 + gg],     Pp[(2 * tt + 1) * 16 + gg]);
        pb.y = pk2(Pp[(2 * tt + 8) * 16 + gg], Pp[(2 * tt + 9) * 16 + gg]);
        pb.z = pk2(Pp[(2 * tt) * 16 + gg + 8],     Pp[(2 * tt + 1) * 16 + gg + 8]);
        pb.w = pk2(Pp[(2 * tt + 8) * 16 + gg + 8], Pp[(2 * tt + 9) * 16 + gg + 8]);
        ((uint4*)(sm + PB_H))[p * 32 + ln] = pb;
    }

    // ---- per-head q/k/v loads (merged buffer, pitch N3)
    const int ghead = blockIdx.x * 8 + wid;
    const int b = ghead >> 4, h = ghead & 15;
    const size_t baseq = (size_t)(b * K_SEQ) * N3 + (size_t)h * HD;
    const size_t baset = (size_t)b * (K_SEQ * D_DIM) + (size_t)h * HD;
    const uint32_t SQ = QKV_O + wid * HEADB;
    const uint32_t SK = SQ + 16 * QP * 2;
    const uint32_t SV = SK + 16 * QP * 2;
#pragma unroll
    for (int t = 0; t < 4; t++) {
        const int c = lane + t * 32;
        const int row = c >> 3, cw = c & 7;
        const uint32_t so = row * (QP * 2) + cw * 16;
        const size_t go = baseq + (size_t)row * N3 + cw * 8;
        *(uint4*)(sm + SQ + so) = *(const uint4*)(QKV + go);
        *(uint4*)(sm + SK + so) = *(const uint4*)(QKV + go + GN);
        *(uint4*)(sm + SV + so) = *(const uint4*)(QKV + go + 2 * GN);
    }
    __syncthreads();

    const uint32_t lrow = (uint32_t)(lane & 15) * (QP * 2);
    const uint32_t lcol8 = (uint32_t)((lane >> 4) * 8) * 2;

    // ---- S = (1/8) Q K^T
    float S0[4] = {0.f, 0.f, 0.f, 0.f};
    float S1[4] = {0.f, 0.f, 0.f, 0.f};
#pragma unroll
    for (int kc = 0; kc < 4; kc++) {
        uint32_t qa0, qa1, qa2, qa3;
        ldsm4(qa0, qa1, qa2, qa3, sb + SQ + lrow + (uint32_t)(kc * 32) + lcol8);
        uint32_t kb0, kb1, kb2, kb3;
        ldsm4(kb0, kb1, kb2, kb3, sb + SK + lrow + (uint32_t)(kc * 32) + lcol8);
        MMA_S(S0, qa0, qa1, qa2, qa3, kb0, kb2);
        MMA_S(S1, qa0, qa1, qa2, qa3, kb1, kb3);
    }
    float* sS = (float*)(sm + SS_O + wid * 1088);
    sS[g * 17 + 2 * tg]             = S0[0] * 0.125f;
    sS[g * 17 + 2 * tg + 1]         = S0[1] * 0.125f;
    sS[(g + 8) * 17 + 2 * tg]       = S0[2] * 0.125f;
    sS[(g + 8) * 17 + 2 * tg + 1]   = S0[3] * 0.125f;
    sS[g * 17 + 2 * tg + 8]         = S1[0] * 0.125f;
    sS[g * 17 + 2 * tg + 9]         = S1[1] * 0.125f;
    sS[(g + 8) * 17 + 2 * tg + 8]   = S1[2] * 0.125f;
    sS[(g + 8) * 17 + 2 * tg + 9]   = S1[3] * 0.125f;
    __syncwarp();

    uint32_t sh[4], sl[4];
    {
        float x0 = sS[(2 * tg) * 17 + g],     x1 = sS[(2 * tg + 1) * 17 + g];
        float x2 = sS[(2 * tg + 8) * 17 + g], x3 = sS[(2 * tg + 9) * 17 + g];
        float y0 = sS[(2 * tg) * 17 + g + 8],     y1 = sS[(2 * tg + 1) * 17 + g + 8];
        float y2 = sS[(2 * tg + 8) * 17 + g + 8], y3 = sS[(2 * tg + 9) * 17 + g + 8];
        split2(x0, x1, sh[0], sl[0]);
        split2(x2, x3, sh[1], sl[1]);
        split2(y0, y1, sh[2], sl[2]);
        split2(y2, y3, sh[3], sl[3]);
    }

    // ---- irrep loop
    const uint4* paH = (const uint4*)(sm + PA_H);
    const uint4* paL = (const uint4*)(sm + PA_L);
    const uint4* pbH = (const uint4*)(sm + PB_H);
    float M0[4] = {0.f, 0.f, 0.f, 0.f};
    float M1[4] = {0.f, 0.f, 0.f, 0.f};
    for (int p = 0; p < NIRR; p++) {
        const uint4 ph = paH[p * 32 + lane];
        const uint4 pl = paL[p * 32 + lane];
        const uint4 pb = pbH[p * 32 + lane];

        float T0[4] = {0.f, 0.f, 0.f, 0.f};
        float T1[4] = {0.f, 0.f, 0.f, 0.f};
        MMA_S(T0, ph.x, ph.y, ph.z, ph.w, sh[0], sh[1]);
        MMA_S(T1, ph.x, ph.y, ph.z, ph.w, sh[2], sh[3]);
        MMA_S(T0, ph.x, ph.y, ph.z, ph.w, sl[0], sl[1]);
        MMA_S(T1, ph.x, ph.y, ph.z, ph.w, sl[2], sl[3]);
        MMA_S(T0, pl.x, pl.y, pl.z, pl.w, sh[0], sh[1]);
        MMA_S(T1, pl.x, pl.y, pl.z, pl.w, sh[2], sh[3]);

        uint32_t tH[4], tL[4];
        split2(T0[0], T0[1], tH[0], tL[0]);
        split2(T0[2], T0[3], tH[1], tL[1]);
        split2(T1[0], T1[1], tH[2], tL[2]);
        split2(T1[2], T1[3], tH[3], tL[3]);

        float z0[4] = {0.f, 0.f, 0.f, 0.f};
        float z1[4] = {0.f, 0.f, 0.f, 0.f};
        MMA_S(z0, tH[0], tH[1], tH[2], tH[3], ph.x, ph.z);
        MMA_S(z1, tH[0], tH[1], tH[2], tH[3], ph.y, ph.w);
        MMA_S(z0, tH[0], tH[1], tH[2], tH[3], pl.x, pl.z);
        MMA_S(z1, tH[0], tH[1], tH[2], tH[3], pl.y, pl.w);
        MMA_S(z0, tL[0], tL[1], tL[2], tL[3], ph.x, ph.z);
        MMA_S(z1, tL[0], tL[1], tL[2], tL[3], ph.y, ph.w);

        const float e00 = __expf(z0[0]), e01 = __expf(z0[1]);
        const float e10 = __expf(z1[0]), e11 = __expf(z1[1]);
        const float e02 = __expf(z0[2]), e03 = __expf(z0[3]);
        const float e12 = __expf(z1[2]), e13 = __expf(z1[3]);
        float sg = e00 + e01 + e10 + e11;
        float s8 = e02 + e03 + e12 + e13;
        sg += __shfl_xor_sync(0xffffffffu, sg, 1);
        sg += __shfl_xor_sync(0xffffffffu, sg, 2);
        s8 += __shfl_xor_sync(0xffffffffu, s8, 1);
        s8 += __shfl_xor_sync(0xffffffffu, s8, 2);
        const float i0 = __frcp_rn(sg), i1 = __frcp_rn(s8);

        uint32_t w0 = pk2(e00 * i0, e01 * i0);
        uint32_t w1 = pk2(e02 * i1, e03 * i1);
        uint32_t w2 = pk2(e10 * i0, e11 * i0);
        uint32_t w3 = pk2(e12 * i1, e13 * i1);

        MMA_S(M0, w0, w1, w2, w3, pb.x, pb.y);
        MMA_S(M1, w0, w1, w2, w3, pb.z, pb.w);
    }

    // ---- out = M * V
    uint32_t mf0 = pk2(M0[0], M0[1]);
    uint32_t mf1 = pk2(M0[2], M0[3]);
    uint32_t mf2 = pk2(M1[0], M1[1]);
    uint32_t mf3 = pk2(M1[2], M1[3]);
#pragma unroll
    for (int nc = 0; nc < 4; nc++) {
        uint32_t vb0, vb1, vb2, vb3;
        ldsm4t(vb0, vb1, vb2, vb3, sb + SV + lrow + (uint32_t)(nc * 32) + lcol8);
        float OA[4] = {0.f, 0.f, 0.f, 0.f};
        float OB[4] = {0.f, 0.f, 0.f, 0.f};
        MMA_S(OA, mf0, mf1, mf2, mf3, vb0, vb1);
        MMA_S(OB, mf0, mf1, mf2, mf3, vb2, vb3);
        __half* dst = Tg + baset;
        const int c0 = nc * 16 + 2 * tg;
        *(uint32_t*)(dst + (size_t)g * D_DIM + c0)           = pk2(OA[0], OA[1]);
        *(uint32_t*)(dst + (size_t)g * D_DIM + c0 + 8)       = pk2(OB[0], OB[1]);
        *(uint32_t*)(dst + (size_t)(g + 8) * D_DIM + c0)     = pk2(OA[2], OA[3]);
        *(uint32_t*)(dst + (size_t)(g + 8) * D_DIM + c0 + 8) = pk2(OB[2], OB[3]);
    }
}

// ---------------- launch -----------------------------------------------------
extern "C" void kernel_launch(void* const* d_in, const int* in_sizes, int n_in,
                              void* d_out, int out_size)
{
    (void)in_sizes; (void)n_in; (void)out_size;
    const float* x    = (const float*)d_in[0];
    const float* proj = (const float*)d_in[1];
    const float* Wq   = (const float*)d_in[2];
    const float* bq   = (const float*)d_in[3];
    const float* Wk   = (const float*)d_in[4];
    const float* bk   = (const float*)d_in[5];
    const float* Wv   = (const float*)d_in[6];
    const float* bv   = (const float*)d_in[7];
    const float* Wo   = (const float*)d_in[8];
    const float* bo   = (const float*)d_in[9];
    float* out = (float*)d_out;

    __half *xh, *qkv, *th, *wt;
    float* gb;
    cudaGetSymbolAddress((void**)&xh, g_xh);
    cudaGetSymbolAddress((void**)&qkv, g_qkv);
    cudaGetSymbolAddress((void**)&th, g_th);
    cudaGetSymbolAddress((void**)&wt, g_wt);
    cudaGetSymbolAddress((void**)&gb, g_bias);

    cudaFuncSetAttribute(gemm_f16<1>, cudaFuncAttributeMaxDynamicSharedMemorySize,
                         SMEM_DYN);
    cudaFuncSetAttribute(gemm_f16<0>, cudaFuncAttributeMaxDynamicSharedMemorySize,
                         SMEM_DYN);
    cudaFuncSetAttribute(psead_attn, cudaFuncAttributeMaxDynamicSharedMemorySize,
                         AT_SMEM);

    const int WSZ = GK * GN;
    const int n4 = GM * GK / 4;

    // bias concat (graph-capturable async D2D copies)
    cudaMemcpyAsync(gb,        bq, GN * sizeof(float), cudaMemcpyDeviceToDevice);
    cudaMemcpyAsync(gb + GN,   bk, GN * sizeof(float), cudaMemcpyDeviceToDevice);
    cudaMemcpyAsync(gb + 2*GN, bv, GN * sizeof(float), cudaMemcpyDeviceToDevice);

    conv_f16<<<(n4 + 255) / 256, 256>>>((const float4*)x, (uint2*)xh, n4);   // k0
    {
        dim3 tg4(GN / 32, GK / 32, 4);
        convT_w4<<<tg4, 256>>>(Wq, Wk, Wv, Wo, wt);                          // k1
    }
    {
        dim3 gg(N3 / 64, GM / 128);   // (48, 128) merged QKV
        gemm_f16<1><<<gg, 256, SMEM_DYN>>>(xh, wt, gb, qkv, N3);             // k2 (ncu slot)
    }
    psead_attn<<<B_SZ * H_NUM / 8, 256, AT_SMEM>>>(qkv, proj, th);           // k3
    {
        dim3 gg(GN / 64, GM / 128);   // (16, 128)
        gemm_f16<0><<<gg, 256, SMEM_DYN>>>(th, wt + 3 * WSZ, bo, out, GN);   // k4
    }
}

// round 16
// speedup vs baseline: 1.9434x; 1.0067x over previous
#include <cuda_runtime.h>
#include <cuda_fp16.h>
#include <cstdint>

// Problem constants
#define B_SZ    1024
#define K_SEQ   16
#define D_DIM   1024
#define H_NUM   16
#define HD      64
#define NIRR    16

#define GM      (B_SZ * K_SEQ)   // 16384
#define GN      D_DIM            // 1024
#define GK      D_DIM            // 1024
#define N3      (3 * GN)         // 3072

// ---------------- scratch (device globals: no allocations allowed) ----------
__device__ __half g_xh[GM * GK];
__device__ __half g_qkv[(size_t)GM * N3];   // merged Q|K|V, pitch 3072
__device__ __half g_th[GM * GN];
__device__ __half g_wt[4][GK * GN];         // transposed weights [N][K], fp16
__device__ float  g_bias[N3];               // concat bq|bk|bv
__device__ uint4  g_pfh[NIRR * 32];         // P A-frag hi
__device__ uint4  g_pfl[NIRR * 32];         // P A-frag lo
__device__ uint4  g_pfb[NIRR * 32];         // P B-frag (for M-MMA)

// ---------------- helpers -----------------------------------------------------
__device__ __forceinline__ uint32_t smem_u32(const void* p) {
    uint32_t a;
    asm("{ .reg .u64 t; cvta.to.shared.u64 t, %1; cvt.u32.u64 %0, t; }"
        : "=r"(a) : "l"(p));
    return a;
}
__device__ __forceinline__ void cp16(uint32_t daddr, const void* g) {
    asm volatile("cp.async.cg.shared.global [%0], [%1], 16;\n"
                 :: "r"(daddr), "l"(g) : "memory");
}
__device__ __forceinline__ void ldsm4(uint32_t& r0, uint32_t& r1,
                                      uint32_t& r2, uint32_t& r3, uint32_t a) {
    asm volatile("ldmatrix.sync.aligned.m8n8.x4.shared.b16 {%0,%1,%2,%3}, [%4];"
                 : "=r"(r0), "=r"(r1), "=r"(r2), "=r"(r3) : "r"(a));
}
__device__ __forceinline__ void ldsm4t(uint32_t& r0, uint32_t& r1,
                                       uint32_t& r2, uint32_t& r3, uint32_t a) {
    asm volatile("ldmatrix.sync.aligned.m8n8.x4.trans.shared.b16 {%0,%1,%2,%3}, [%4];"
                 : "=r"(r0), "=r"(r1), "=r"(r2), "=r"(r3) : "r"(a));
}
#define MMA_F16(d, a, b) asm volatile( \
    "mma.sync.aligned.m16n8k16.row.col.f32.f16.f16.f32 " \
    "{%0,%1,%2,%3}, {%4,%5,%6,%7}, {%8,%9}, {%0,%1,%2,%3};\n" \
    : "+f"(d[0]), "+f"(d[1]), "+f"(d[2]), "+f"(d[3]) \
    : "r"(a[0]), "r"(a[1]), "r"(a[2]), "r"(a[3]), "r"(b[0]), "r"(b[1]))

#define MMA_S(d, a0, a1, a2, a3, b0, b1) asm volatile( \
    "mma.sync.aligned.m16n8k16.row.col.f32.f16.f16.f32 " \
    "{%0,%1,%2,%3}, {%4,%5,%6,%7}, {%8,%9}, {%0,%1,%2,%3};\n" \
    : "+f"(d[0]), "+f"(d[1]), "+f"(d[2]), "+f"(d[3]) \
    : "r"(a0), "r"(a1), "r"(a2), "r"(a3), "r"(b0), "r"(b1))

__device__ __forceinline__ void split2(float x, float y, uint32_t& hi, uint32_t& lo) {
    __half2 h = __floats2half2_rn(x, y);
    float2 hf = __half22float2(h);
    __half2 l = __floats2half2_rn(x - hf.x, y - hf.y);
    hi = *(uint32_t*)&h;
    lo = *(uint32_t*)&l;
}
__device__ __forceinline__ uint32_t pk2(float x, float y) {
    __half2 h = __floats2half2_rn(x, y);
    return *(uint32_t*)&h;
}

// ---------------- fp32 -> fp16 convert (contiguous) --------------------------
__global__ __launch_bounds__(256) void conv_f16(
    const float4* __restrict__ src, uint2* __restrict__ dst, int n4)
{
    int i = blockIdx.x * blockDim.x + threadIdx.x;
    if (i >= n4) return;
    float4 v = src[i];
    __half2 h01 = __floats2half2_rn(v.x, v.y);
    __half2 h23 = __floats2half2_rn(v.z, v.w);
    uint2 o;
    o.x = *(const uint32_t*)&h01;
    o.y = *(const uint32_t*)&h23;
    dst[i] = o;
}

// ---------------- fp32 W[K][N] -> fp16 transposed [N][K], 4 weights ----------
__global__ __launch_bounds__(256) void convT_w4(
    const float* __restrict__ W0, const float* __restrict__ W1,
    const float* __restrict__ W2, const float* __restrict__ W3,
    __half* __restrict__ T)
{
    __shared__ float tile[32][33];
    const float* W = (blockIdx.z == 0) ? W0 : (blockIdx.z == 1) ? W1
                   : (blockIdx.z == 2) ? W2 : W3;
    __half* Tz = T + (size_t)blockIdx.z * GK * GN;
    const int tx = threadIdx.x & 31, ty = threadIdx.x >> 5;
    const int k0 = blockIdx.y * 32, n0 = blockIdx.x * 32;
#pragma unroll
    for (int r = 0; r < 4; r++)
        tile[ty + r * 8][tx] = W[(size_t)(k0 + ty + r * 8) * GN + n0 + tx];
    __syncthreads();
#pragma unroll
    for (int r = 0; r < 4; r++) {
        size_t o = (size_t)(n0 + ty + r * 8) * GK + k0 + tx;
        Tz[o] = __float2half(tile[tx][ty + r * 8]);
    }
}

// ---------------- one-off: P -> MMA fragments (global) -----------------------
__global__ __launch_bounds__(512) void prep_pfrag(
    const float* __restrict__ proj,
    uint4* __restrict__ pfh, uint4* __restrict__ pfl, uint4* __restrict__ pfb)
{
    const int s = threadIdx.x;             // 0..511
    const int p = s >> 5, ln = s & 31;
    const int gg = ln >> 2, tt = ln & 3;
    const float* Pp = proj + p * 256;
    float a0x = Pp[gg * 16 + 2 * tt],       a0y = Pp[gg * 16 + 2 * tt + 1];
    float a1x = Pp[(gg + 8) * 16 + 2 * tt], a1y = Pp[(gg + 8) * 16 + 2 * tt + 1];
    float a2x = Pp[gg * 16 + 2 * tt + 8],   a2y = Pp[gg * 16 + 2 * tt + 9];
    float a3x = Pp[(gg + 8) * 16 + 2 * tt + 8], a3y = Pp[(gg + 8) * 16 + 2 * tt + 9];
    uint4 ph, pl;
    split2(a0x, a0y, ph.x, pl.x);
    split2(a1x, a1y, ph.y, pl.y);
    split2(a2x, a2y, ph.z, pl.z);
    split2(a3x, a3y, ph.w, pl.w);
    pfh[s] = ph;
    pfl[s] = pl;
    uint4 pb;
    pb.x = pk2(Pp[(2 * tt) * 16 + gg],     Pp[(2 * tt + 1) * 16 + gg]);
    pb.y = pk2(Pp[(2 * tt + 8) * 16 + gg], Pp[(2 * tt + 9) * 16 + gg]);
    pb.z = pk2(Pp[(2 * tt) * 16 + gg + 8],     Pp[(2 * tt + 1) * 16 + gg + 8]);
    pb.w = pk2(Pp[(2 * tt + 8) * 16 + gg + 8], Pp[(2 * tt + 9) * 16 + gg + 8]);
    pfb[s] = pb;
}

// ---------------- fp16 GEMM on mma.sync (HMMA) — R13 config, validated -------
#define STG_BYTES 24576
#define SMEM_DYN (2 * STG_BYTES)        // 49152
#define NITER (GK / 64)                 // 16

template <int OUT_HALF>
__global__ __launch_bounds__(256, 4) void gemm_f16(
    const __half* __restrict__ A, const __half* __restrict__ B,
    const float* __restrict__ bias, void* __restrict__ Cv, int ldc)
{
    extern __shared__ __align__(1024) char smem[];
    const uint32_t sb = smem_u32(smem);
    const int tid  = threadIdx.x;
    const int lane = tid & 31;
    const int wid  = tid >> 5;
    const int wm   = wid & 3;
    const int wn   = wid >> 2;
    const int brow = blockIdx.y * 128;
    const int bcol = blockIdx.x * 64;

    const __half* pA[4];
    uint32_t sA[4];
#pragma unroll
    for (int t = 0; t < 4; t++) {
        const int c = tid + t * 256;
        const int row = c >> 3, cw = c & 7;
        sA[t] = (uint32_t)(row * 128 + ((cw ^ (row & 7)) << 4));
        pA[t] = A + (size_t)(brow + row) * GK + cw * 8;
    }
    const __half* pB[2];
    uint32_t sB[2];
#pragma unroll
    for (int t = 0; t < 2; t++) {
        const int c = tid + t * 256;
        const int row = c >> 3, cw = c & 7;
        sB[t] = (uint32_t)(16384 + row * 128 + ((cw ^ (row & 7)) << 4));
        pB[t] = B + (size_t)(bcol + row) * GK + cw * 8;
    }

#define FILL(stg, k0)                                                        \
    do {                                                                     \
        const uint32_t so_ = sb + (uint32_t)(stg) * STG_BYTES;               \
        _Pragma("unroll")                                                    \
        for (int t_ = 0; t_ < 4; t_++) cp16(so_ + sA[t_], pA[t_] + (k0));    \
        _Pragma("unroll")                                                    \
        for (int t_ = 0; t_ < 2; t_++) cp16(so_ + sB[t_], pB[t_] + (k0));    \
        asm volatile("cp.async.commit_group;" ::: "memory");                 \
    } while (0)

    const int lsw  = lane & 7;
    const int a_kc = (lane >> 4) & 1;
    const int b_kc = (lane >> 3) & 1;
    uint32_t a_ro[2], b_ro[2];
#pragma unroll
    for (int mt = 0; mt < 2; mt++)
        a_ro[mt] = (uint32_t)(wm * 32 + mt * 16 + (lane & 7) + ((lane >> 3) & 1) * 8) * 128;
#pragma unroll
    for (int np = 0; np < 2; np++)
        b_ro[np] = (uint32_t)(wn * 32 + np * 16 + (lane & 7) + ((lane >> 4) & 1) * 8) * 128
                   + 16384;

    float acc[2][4][4];
#pragma unroll
    for (int mt = 0; mt < 2; mt++)
#pragma unroll
        for (int nt = 0; nt < 4; nt++)
#pragma unroll
            for (int q = 0; q < 4; q++) acc[mt][nt][q] = 0.f;

    FILL(0, 0);
    FILL(1, 64);

    for (int s = 0; s < NITER; s++) {
        if (s == NITER - 1) asm volatile("cp.async.wait_group 0;" ::: "memory");
        else                asm volatile("cp.async.wait_group 1;" ::: "memory");
        __syncthreads();

        const uint32_t stg = sb + (uint32_t)(s & 1) * STG_BYTES;
#pragma unroll
        for (int kk = 0; kk < 4; kk++) {
            uint32_t a[2][4];
#pragma unroll
            for (int mt = 0; mt < 2; mt++) {
                const uint32_t ad = stg + a_ro[mt]
                    + ((uint32_t)((kk * 2 + a_kc) ^ lsw) << 4);
                ldsm4(a[mt][0], a[mt][1], a[mt][2], a[mt][3], ad);
            }
            uint32_t b[4][2];
#pragma unroll
            for (int np = 0; np < 2; np++) {
                const uint32_t bd = stg + b_ro[np]
                    + ((uint32_t)((kk * 2 + b_kc) ^ lsw) << 4);
                ldsm4(b[2 * np][0], b[2 * np][1],
                      b[2 * np + 1][0], b[2 * np + 1][1], bd);
            }
#pragma unroll
            for (int mt = 0; mt < 2; mt++)
#pragma unroll
                for (int nt = 0; nt < 4; nt++)
                    MMA_F16(acc[mt][nt], a[mt], b[nt]);
        }

        if (s + 2 < NITER) {
            __syncthreads();          // all reads of this slot done
            FILL(s & 1, (s + 2) * 64);
        }
    }

#pragma unroll
    for (int mt = 0; mt < 2; mt++) {
        const int row = brow + wm * 32 + mt * 16 + (lane >> 2);
#pragma unroll
        for (int nt = 0; nt < 4; nt++) {
            const int col = bcol + wn * 32 + nt * 8 + (lane & 3) * 2;
            const float b0 = __ldg(bias + col), b1 = __ldg(bias + col + 1);
            if (OUT_HALF) {
                __half* C = (__half*)Cv;
                __half2 p0 = __floats2half2_rn(acc[mt][nt][0] + b0,
                                               acc[mt][nt][1] + b1);
                __half2 p1 = __floats2half2_rn(acc[mt][nt][2] + b0,
                                               acc[mt][nt][3] + b1);
                *(uint32_t*)&C[(size_t)row * ldc + col] = *(uint32_t*)&p0;
                *(uint32_t*)&C[(size_t)(row + 8) * ldc + col] = *(uint32_t*)&p1;
            } else {
                float* C = (float*)Cv;
                float2 o;
                o.x = acc[mt][nt][0] + b0;
                o.y = acc[mt][nt][1] + b1;
                *(float2*)&C[(size_t)row * ldc + col] = o;
                o.x = acc[mt][nt][2] + b0;
                o.y = acc[mt][nt][3] + b1;
                *(float2*)&C[(size_t)(row + 8) * ldc + col] = o;
            }
        }
    }
}

// ---------------- per-(b,h) irrep attention: tensor-core, global P-frags -----
// 1 warp per head, 8 heads per block. P fragments precomputed in global
// (L1-broadcast); smem = QKV staging + S only -> 64000 B -> 3 CTAs/SM.
#define HEADB 6912
#define SS_O  (8 * HEADB)              // 55296
#define AT_SMEM (SS_O + 8 * 1088)      // 64000
#define QP    72                        // halves per row (144B pitch)

__global__ __launch_bounds__(256) void psead_attn(
    const __half* __restrict__ QKV, __half* __restrict__ Tg,
    const uint4* __restrict__ pfh, const uint4* __restrict__ pfl,
    const uint4* __restrict__ pfb)
{
    extern __shared__ __align__(16) char sm[];
    const uint32_t sb = smem_u32(sm);
    const int tid  = threadIdx.x;
    const int wid  = tid >> 5;
    const int lane = tid & 31;
    const int g    = lane >> 2;
    const int tg   = lane & 3;

    // ---- per-head q/k/v loads (merged buffer, pitch N3); warp-private
    const int ghead = blockIdx.x * 8 + wid;
    const int b = ghead >> 4, h = ghead & 15;
    const size_t baseq = (size_t)(b * K_SEQ) * N3 + (size_t)h * HD;
    const size_t baset = (size_t)b * (K_SEQ * D_DIM) + (size_t)h * HD;
    const uint32_t SQ = wid * HEADB;
    const uint32_t SK = SQ + 16 * QP * 2;
    const uint32_t SV = SK + 16 * QP * 2;
#pragma unroll
    for (int t = 0; t < 4; t++) {
        const int c = lane + t * 32;
        const int row = c >> 3, cw = c & 7;
        const uint32_t so = row * (QP * 2) + cw * 16;
        const size_t go = baseq + (size_t)row * N3 + cw * 8;
        *(uint4*)(sm + SQ + so) = *(const uint4*)(QKV + go);
        *(uint4*)(sm + SK + so) = *(const uint4*)(QKV + go + GN);
        *(uint4*)(sm + SV + so) = *(const uint4*)(QKV + go + 2 * GN);
    }
    __syncwarp();

    const uint32_t lrow = (uint32_t)(lane & 15) * (QP * 2);
    const uint32_t lcol8 = (uint32_t)((lane >> 4) * 8) * 2;

    // ---- S = (1/8) Q K^T
    float S0[4] = {0.f, 0.f, 0.f, 0.f};
    float S1[4] = {0.f, 0.f, 0.f, 0.f};
#pragma unroll
    for (int kc = 0; kc < 4; kc++) {
        uint32_t qa0, qa1, qa2, qa3;
        ldsm4(qa0, qa1, qa2, qa3, sb + SQ + lrow + (uint32_t)(kc * 32) + lcol8);
        uint32_t kb0, kb1, kb2, kb3;
        ldsm4(kb0, kb1, kb2, kb3, sb + SK + lrow + (uint32_t)(kc * 32) + lcol8);
        MMA_S(S0, qa0, qa1, qa2, qa3, kb0, kb2);
        MMA_S(S1, qa0, qa1, qa2, qa3, kb1, kb3);
    }
    float* sS = (float*)(sm + SS_O + wid * 1088);
    sS[g * 17 + 2 * tg]             = S0[0] * 0.125f;
    sS[g * 17 + 2 * tg + 1]         = S0[1] * 0.125f;
    sS[(g + 8) * 17 + 2 * tg]       = S0[2] * 0.125f;
    sS[(g + 8) * 17 + 2 * tg + 1]   = S0[3] * 0.125f;
    sS[g * 17 + 2 * tg + 8]         = S1[0] * 0.125f;
    sS[g * 17 + 2 * tg + 9]         = S1[1] * 0.125f;
    sS[(g + 8) * 17 + 2 * tg + 8]   = S1[2] * 0.125f;
    sS[(g + 8) * 17 + 2 * tg + 9]   = S1[3] * 0.125f;
    __syncwarp();

    uint32_t sh[4], sl[4];
    {
        float x0 = sS[(2 * tg) * 17 + g],     x1 = sS[(2 * tg + 1) * 17 + g];
        float x2 = sS[(2 * tg + 8) * 17 + g], x3 = sS[(2 * tg + 9) * 17 + g];
        float y0 = sS[(2 * tg) * 17 + g + 8],     y1 = sS[(2 * tg + 1) * 17 + g + 8];
        float y2 = sS[(2 * tg + 8) * 17 + g + 8], y3 = sS[(2 * tg + 9) * 17 + g + 8];
        split2(x0, x1, sh[0], sl[0]);
        split2(x2, x3, sh[1], sl[1]);
        split2(y0, y1, sh[2], sl[2]);
        split2(y2, y3, sh[3], sl[3]);
    }

    // ---- irrep loop (P fragments from global, L1-broadcast)
    float M0[4] = {0.f, 0.f, 0.f, 0.f};
    float M1[4] = {0.f, 0.f, 0.f, 0.f};
    for (int p = 0; p < NIRR; p++) {
        const uint4 ph = __ldg(pfh + p * 32 + lane);
        const uint4 pl = __ldg(pfl + p * 32 + lane);
        const uint4 pb = __ldg(pfb + p * 32 + lane);

        float T0[4] = {0.f, 0.f, 0.f, 0.f};
        float T1[4] = {0.f, 0.f, 0.f, 0.f};
        MMA_S(T0, ph.x, ph.y, ph.z, ph.w, sh[0], sh[1]);
        MMA_S(T1, ph.x, ph.y, ph.z, ph.w, sh[2], sh[3]);
        MMA_S(T0, ph.x, ph.y, ph.z, ph.w, sl[0], sl[1]);
        MMA_S(T1, ph.x, ph.y, ph.z, ph.w, sl[2], sl[3]);
        MMA_S(T0, pl.x, pl.y, pl.z, pl.w, sh[0], sh[1]);
        MMA_S(T1, pl.x, pl.y, pl.z, pl.w, sh[2], sh[3]);

        uint32_t tH[4], tL[4];
        split2(T0[0], T0[1], tH[0], tL[0]);
        split2(T0[2], T0[3], tH[1], tL[1]);
        split2(T1[0], T1[1], tH[2], tL[2]);
        split2(T1[2], T1[3], tH[3], tL[3]);

        float z0[4] = {0.f, 0.f, 0.f, 0.f};
        float z1[4] = {0.f, 0.f, 0.f, 0.f};
        MMA_S(z0, tH[0], tH[1], tH[2], tH[3], ph.x, ph.z);
        MMA_S(z1, tH[0], tH[1], tH[2], tH[3], ph.y, ph.w);
        MMA_S(z0, tH[0], tH[1], tH[2], tH[3], pl.x, pl.z);
        MMA_S(z1, tH[0], tH[1], tH[2], tH[3], pl.y, pl.w);
        MMA_S(z0, tL[0], tL[1], tL[2], tL[3], ph.x, ph.z);
        MMA_S(z1, tL[0], tL[1], tL[2], tL[3], ph.y, ph.w);

        const float e00 = __expf(z0[0]), e01 = __expf(z0[1]);
        const float e10 = __expf(z1[0]), e11 = __expf(z1[1]);
        const float e02 = __expf(z0[2]), e03 = __expf(z0[3]);
        const float e12 = __expf(z1[2]), e13 = __expf(z1[3]);
        float sg = e00 + e01 + e10 + e11;
        float s8 = e02 + e03 + e12 + e13;
        sg += __shfl_xor_sync(0xffffffffu, sg, 1);
        sg += __shfl_xor_sync(0xffffffffu, sg, 2);
        s8 += __shfl_xor_sync(0xffffffffu, s8, 1);
        s8 += __shfl_xor_sync(0xffffffffu, s8, 2);
        const float i0 = __frcp_rn(sg), i1 = __frcp_rn(s8);

        uint32_t w0 = pk2(e00 * i0, e01 * i0);
        uint32_t w1 = pk2(e02 * i1, e03 * i1);
        uint32_t w2 = pk2(e10 * i0, e11 * i0);
        uint32_t w3 = pk2(e12 * i1, e13 * i1);

        MMA_S(M0, w0, w1, w2, w3, pb.x, pb.y);
        MMA_S(M1, w0, w1, w2, w3, pb.z, pb.w);
    }

    // ---- out = M * V
    uint32_t mf0 = pk2(M0[0], M0[1]);
    uint32_t mf1 = pk2(M0[2], M0[3]);
    uint32_t mf2 = pk2(M1[0], M1[1]);
    uint32_t mf3 = pk2(M1[2], M1[3]);
#pragma unroll
    for (int nc = 0; nc < 4; nc++) {
        uint32_t vb0, vb1, vb2, vb3;
        ldsm4t(vb0, vb1, vb2, vb3, sb + SV + lrow + (uint32_t)(nc * 32) + lcol8);
        float OA[4] = {0.f, 0.f, 0.f, 0.f};
        float OB[4] = {0.f, 0.f, 0.f, 0.f};
        MMA_S(OA, mf0, mf1, mf2, mf3, vb0, vb1);
        MMA_S(OB, mf0, mf1, mf2, mf3, vb2, vb3);
        __half* dst = Tg + baset;
        const int c0 = nc * 16 + 2 * tg;
        *(uint32_t*)(dst + (size_t)g * D_DIM + c0)           = pk2(OA[0], OA[1]);
        *(uint32_t*)(dst + (size_t)g * D_DIM + c0 + 8)       = pk2(OB[0], OB[1]);
        *(uint32_t*)(dst + (size_t)(g + 8) * D_DIM + c0)     = pk2(OA[2], OA[3]);
        *(uint32_t*)(dst + (size_t)(g + 8) * D_DIM + c0 + 8) = pk2(OB[2], OB[3]);
    }
}

// ---------------- launch -----------------------------------------------------
extern "C" void kernel_launch(void* const* d_in, const int* in_sizes, int n_in,
                              void* d_out, int out_size)
{
    (void)in_sizes; (void)n_in; (void)out_size;
    const float* x    = (const float*)d_in[0];
    const float* proj = (const float*)d_in[1];
    const float* Wq   = (const float*)d_in[2];
    const float* bq   = (const float*)d_in[3];
    const float* Wk   = (const float*)d_in[4];
    const float* bk   = (const float*)d_in[5];
    const float* Wv   = (const float*)d_in[6];
    const float* bv   = (const float*)d_in[7];
    const float* Wo   = (const float*)d_in[8];
    const float* bo   = (const float*)d_in[9];
    float* out = (float*)d_out;

    __half *xh, *qkv, *th, *wt;
    float* gb;
    uint4 *pfh, *pfl, *pfb;
    cudaGetSymbolAddress((void**)&xh, g_xh);
    cudaGetSymbolAddress((void**)&qkv, g_qkv);
    cudaGetSymbolAddress((void**)&th, g_th);
    cudaGetSymbolAddress((void**)&wt, g_wt);
    cudaGetSymbolAddress((void**)&gb, g_bias);
    cudaGetSymbolAddress((void**)&pfh, g_pfh);
    cudaGetSymbolAddress((void**)&pfl, g_pfl);
    cudaGetSymbolAddress((void**)&pfb, g_pfb);

    cudaFuncSetAttribute(gemm_f16<1>, cudaFuncAttributeMaxDynamicSharedMemorySize,
                         SMEM_DYN);
    cudaFuncSetAttribute(gemm_f16<0>, cudaFuncAttributeMaxDynamicSharedMemorySize,
                         SMEM_DYN);
    cudaFuncSetAttribute(psead_attn, cudaFuncAttributeMaxDynamicSharedMemorySize,
                         AT_SMEM);

    const int WSZ = GK * GN;
    const int n4 = GM * GK / 4;

    // bias concat (graph-capturable async D2D copies)
    cudaMemcpyAsync(gb,        bq, GN * sizeof(float), cudaMemcpyDeviceToDevice);
    cudaMemcpyAsync(gb + GN,   bk, GN * sizeof(float), cudaMemcpyDeviceToDevice);
    cudaMemcpyAsync(gb + 2*GN, bv, GN * sizeof(float), cudaMemcpyDeviceToDevice);

    conv_f16<<<(n4 + 255) / 256, 256>>>((const float4*)x, (uint2*)xh, n4);   // k0
    prep_pfrag<<<1, 512>>>(proj, pfh, pfl, pfb);                             // k1
    {
        dim3 tg4(GN / 32, GK / 32, 4);
        convT_w4<<<tg4, 256>>>(Wq, Wk, Wv, Wo, wt);                          // k2
    }
    {
        dim3 gg(N3 / 64, GM / 128);   // (48, 128) merged QKV
        gemm_f16<1><<<gg, 256, SMEM_DYN>>>(xh, wt, gb, qkv, N3);             // k3
    }
    psead_attn<<<B_SZ * H_NUM / 8, 256, AT_SMEM>>>(qkv, th, pfh, pfl, pfb);  // k4
    {
        dim3 gg(GN / 64, GM / 128);   // (16, 128)
        gemm_f16<0><<<gg, 256, SMEM_DYN>>>(th, wt + 3 * WSZ, bo, out, GN);   // k5
    }
}

// round 17
// speedup vs baseline: 1.9873x; 1.0226x over previous
#include <cuda_runtime.h>
#include <cuda_fp16.h>
#include <cstdint>

// Problem constants
#define B_SZ    1024
#define K_SEQ   16
#define D_DIM   1024
#define H_NUM   16
#define HD      64
#define NIRR    16

#define GM      (B_SZ * K_SEQ)   // 16384
#define GN      D_DIM            // 1024
#define GK      D_DIM            // 1024
#define N3      (3 * GN)         // 3072

// ---------------- scratch (device globals: no allocations allowed) ----------
__device__ __half g_xh[GM * GK];
__device__ __half g_qkv[(size_t)GM * N3];   // merged Q|K|V, pitch 3072
__device__ __half g_th[GM * GN];
__device__ __half g_wt[4][GK * GN];         // transposed weights [N][K], fp16
__device__ float  g_bias[N3];               // concat bq|bk|bv
__device__ uint4  g_pfh[NIRR * 32];         // P A-frag hi
__device__ uint4  g_pfl[NIRR * 32];         // P A-frag lo
__device__ uint4  g_pfb[NIRR * 32];         // P B-frag (for M-MMA)

// ---------------- helpers -----------------------------------------------------
__device__ __forceinline__ uint32_t smem_u32(const void* p) {
    uint32_t a;
    asm("{ .reg .u64 t; cvta.to.shared.u64 t, %1; cvt.u32.u64 %0, t; }"
        : "=r"(a) : "l"(p));
    return a;
}
__device__ __forceinline__ void cp16(uint32_t daddr, const void* g) {
    asm volatile("cp.async.cg.shared.global [%0], [%1], 16;\n"
                 :: "r"(daddr), "l"(g) : "memory");
}
__device__ __forceinline__ void ldsm4(uint32_t& r0, uint32_t& r1,
                                      uint32_t& r2, uint32_t& r3, uint32_t a) {
    asm volatile("ldmatrix.sync.aligned.m8n8.x4.shared.b16 {%0,%1,%2,%3}, [%4];"
                 : "=r"(r0), "=r"(r1), "=r"(r2), "=r"(r3) : "r"(a));
}
__device__ __forceinline__ void ldsm4t(uint32_t& r0, uint32_t& r1,
                                       uint32_t& r2, uint32_t& r3, uint32_t a) {
    asm volatile("ldmatrix.sync.aligned.m8n8.x4.trans.shared.b16 {%0,%1,%2,%3}, [%4];"
                 : "=r"(r0), "=r"(r1), "=r"(r2), "=r"(r3) : "r"(a));
}
#define MMA_F16(d, a, b) asm volatile( \
    "mma.sync.aligned.m16n8k16.row.col.f32.f16.f16.f32 " \
    "{%0,%1,%2,%3}, {%4,%5,%6,%7}, {%8,%9}, {%0,%1,%2,%3};\n" \
    : "+f"(d[0]), "+f"(d[1]), "+f"(d[2]), "+f"(d[3]) \
    : "r"(a[0]), "r"(a[1]), "r"(a[2]), "r"(a[3]), "r"(b[0]), "r"(b[1]))

#define MMA_S(d, a0, a1, a2, a3, b0, b1) asm volatile( \
    "mma.sync.aligned.m16n8k16.row.col.f32.f16.f16.f32 " \
    "{%0,%1,%2,%3}, {%4,%5,%6,%7}, {%8,%9}, {%0,%1,%2,%3};\n" \
    : "+f"(d[0]), "+f"(d[1]), "+f"(d[2]), "+f"(d[3]) \
    : "r"(a0), "r"(a1), "r"(a2), "r"(a3), "r"(b0), "r"(b1))

__device__ __forceinline__ void split2(float x, float y, uint32_t& hi, uint32_t& lo) {
    __half2 h = __floats2half2_rn(x, y);
    float2 hf = __half22float2(h);
    __half2 l = __floats2half2_rn(x - hf.x, y - hf.y);
    hi = *(uint32_t*)&h;
    lo = *(uint32_t*)&l;
}
__device__ __forceinline__ uint32_t pk2(float x, float y) {
    __half2 h = __floats2half2_rn(x, y);
    return *(uint32_t*)&h;
}

// ---------------- fused prep: x->fp16, W^T->fp16, P-frags, bias concat -------
// grid.x = 8193 blocks, 256 threads.
//   [0, 4096)     : x fp32 -> fp16 (each block: 1024 float4)
//   [4096, 8192)  : weight transpose+convert (4 weights x 1024 tiles)
//   8192          : P fragments + bias concat
__global__ __launch_bounds__(256) void prep_all(
    const float4* __restrict__ x4, const float* __restrict__ proj,
    const float* __restrict__ Wq, const float* __restrict__ Wk,
    const float* __restrict__ Wv, const float* __restrict__ Wo,
    const float* __restrict__ bq, const float* __restrict__ bk,
    const float* __restrict__ bv,
    uint2* __restrict__ xh, __half* __restrict__ wt,
    uint4* __restrict__ pfh, uint4* __restrict__ pfl, uint4* __restrict__ pfb,
    float* __restrict__ gb)
{
    __shared__ float tile[32][33];
    const int bid = blockIdx.x;
    const int tid = threadIdx.x;

    if (bid < 4096) {
        // ---- x conversion: 4096 blocks x 1024 float4
        const int base = bid * 1024 + tid;
#pragma unroll
        for (int k = 0; k < 4; k++) {
            const int i = base + k * 256;
            float4 v = x4[i];
            __half2 h01 = __floats2half2_rn(v.x, v.y);
            __half2 h23 = __floats2half2_rn(v.z, v.w);
            uint2 o;
            o.x = *(const uint32_t*)&h01;
            o.y = *(const uint32_t*)&h23;
            xh[i] = o;
        }
    } else if (bid < 8192) {
        // ---- weight transpose: local = z*1024 + (by*32 + bx)
        const int local = bid - 4096;
        const int z = local >> 10;
        const int rem = local & 1023;
        const int bx = rem & 31, by = rem >> 5;
        const float* W = (z == 0) ? Wq : (z == 1) ? Wk : (z == 2) ? Wv : Wo;
        __half* Tz = wt + (size_t)z * GK * GN;
        const int tx = tid & 31, ty = tid >> 5;
        const int k0 = by * 32, n0 = bx * 32;
#pragma unroll
        for (int r = 0; r < 4; r++)
            tile[ty + r * 8][tx] = W[(size_t)(k0 + ty + r * 8) * GN + n0 + tx];
        __syncthreads();
#pragma unroll
        for (int r = 0; r < 4; r++) {
            size_t o = (size_t)(n0 + ty + r * 8) * GK + k0 + tx;
            Tz[o] = __float2half(tile[tx][ty + r * 8]);
        }
    } else {
        // ---- P fragments (512 slots, 2 per thread) + bias concat
        for (int s = tid; s < NIRR * 32; s += 256) {
            const int p = s >> 5, ln = s & 31;
            const int gg = ln >> 2, tt = ln & 3;
            const float* Pp = proj + p * 256;
            float a0x = Pp[gg * 16 + 2 * tt],       a0y = Pp[gg * 16 + 2 * tt + 1];
            float a1x = Pp[(gg + 8) * 16 + 2 * tt], a1y = Pp[(gg + 8) * 16 + 2 * tt + 1];
            float a2x = Pp[gg * 16 + 2 * tt + 8],   a2y = Pp[gg * 16 + 2 * tt + 9];
            float a3x = Pp[(gg + 8) * 16 + 2 * tt + 8], a3y = Pp[(gg + 8) * 16 + 2 * tt + 9];
            uint4 ph, pl;
            split2(a0x, a0y, ph.x, pl.x);
            split2(a1x, a1y, ph.y, pl.y);
            split2(a2x, a2y, ph.z, pl.z);
            split2(a3x, a3y, ph.w, pl.w);
            pfh[s] = ph;
            pfl[s] = pl;
            uint4 pb;
            pb.x = pk2(Pp[(2 * tt) * 16 + gg],     Pp[(2 * tt + 1) * 16 + gg]);
            pb.y = pk2(Pp[(2 * tt + 8) * 16 + gg], Pp[(2 * tt + 9) * 16 + gg]);
            pb.z = pk2(Pp[(2 * tt) * 16 + gg + 8],     Pp[(2 * tt + 1) * 16 + gg + 8]);
            pb.w = pk2(Pp[(2 * tt + 8) * 16 + gg + 8], Pp[(2 * tt + 9) * 16 + gg + 8]);
            pfb[s] = pb;
        }
        // bias concat: 3 x 1024 floats
        for (int i = tid; i < GN; i += 256) {
            gb[i]          = bq[i];
            gb[i + GN]     = bk[i];
            gb[i + 2 * GN] = bv[i];
        }
    }
}

// ---------------- fp16 GEMM on mma.sync (HMMA) — R13 config, validated -------
#define STG_BYTES 24576
#define SMEM_DYN (2 * STG_BYTES)        // 49152
#define NITER (GK / 64)                 // 16

template <int OUT_HALF>
__global__ __launch_bounds__(256, 4) void gemm_f16(
    const __half* __restrict__ A, const __half* __restrict__ B,
    const float* __restrict__ bias, void* __restrict__ Cv, int ldc)
{
    extern __shared__ __align__(1024) char smem[];
    const uint32_t sb = smem_u32(smem);
    const int tid  = threadIdx.x;
    const int lane = tid & 31;
    const int wid  = tid >> 5;
    const int wm   = wid & 3;
    const int wn   = wid >> 2;
    const int brow = blockIdx.y * 128;
    const int bcol = blockIdx.x * 64;

    const __half* pA[4];
    uint32_t sA[4];
#pragma unroll
    for (int t = 0; t < 4; t++) {
        const int c = tid + t * 256;
        const int row = c >> 3, cw = c & 7;
        sA[t] = (uint32_t)(row * 128 + ((cw ^ (row & 7)) << 4));
        pA[t] = A + (size_t)(brow + row) * GK + cw * 8;
    }
    const __half* pB[2];
    uint32_t sB[2];
#pragma unroll
    for (int t = 0; t < 2; t++) {
        const int c = tid + t * 256;
        const int row = c >> 3, cw = c & 7;
        sB[t] = (uint32_t)(16384 + row * 128 + ((cw ^ (row & 7)) << 4));
        pB[t] = B + (size_t)(bcol + row) * GK + cw * 8;
    }

#define FILL(stg, k0)                                                        \
    do {                                                                     \
        const uint32_t so_ = sb + (uint32_t)(stg) * STG_BYTES;               \
        _Pragma("unroll")                                                    \
        for (int t_ = 0; t_ < 4; t_++) cp16(so_ + sA[t_], pA[t_] + (k0));    \
        _Pragma("unroll")                                                    \
        for (int t_ = 0; t_ < 2; t_++) cp16(so_ + sB[t_], pB[t_] + (k0));    \
        asm volatile("cp.async.commit_group;" ::: "memory");                 \
    } while (0)

    const int lsw  = lane & 7;
    const int a_kc = (lane >> 4) & 1;
    const int b_kc = (lane >> 3) & 1;
    uint32_t a_ro[2], b_ro[2];
#pragma unroll
    for (int mt = 0; mt < 2; mt++)
        a_ro[mt] = (uint32_t)(wm * 32 + mt * 16 + (lane & 7) + ((lane >> 3) & 1) * 8) * 128;
#pragma unroll
    for (int np = 0; np < 2; np++)
        b_ro[np] = (uint32_t)(wn * 32 + np * 16 + (lane & 7) + ((lane >> 4) & 1) * 8) * 128
                   + 16384;

    float acc[2][4][4];
#pragma unroll
    for (int mt = 0; mt < 2; mt++)
#pragma unroll
        for (int nt = 0; nt < 4; nt++)
#pragma unroll
            for (int q = 0; q < 4; q++) acc[mt][nt][q] = 0.f;

    FILL(0, 0);
    FILL(1, 64);

    for (int s = 0; s < NITER; s++) {
        if (s == NITER - 1) asm volatile("cp.async.wait_group 0;" ::: "memory");
        else                asm volatile("cp.async.wait_group 1;" ::: "memory");
        __syncthreads();

        const uint32_t stg = sb + (uint32_t)(s & 1) * STG_BYTES;
#pragma unroll
        for (int kk = 0; kk < 4; kk++) {
            uint32_t a[2][4];
#pragma unroll
            for (int mt = 0; mt < 2; mt++) {
                const uint32_t ad = stg + a_ro[mt]
                    + ((uint32_t)((kk * 2 + a_kc) ^ lsw) << 4);
                ldsm4(a[mt][0], a[mt][1], a[mt][2], a[mt][3], ad);
            }
            uint32_t b[4][2];
#pragma unroll
            for (int np = 0; np < 2; np++) {
                const uint32_t bd = stg + b_ro[np]
                    + ((uint32_t)((kk * 2 + b_kc) ^ lsw) << 4);
                ldsm4(b[2 * np][0], b[2 * np][1],
                      b[2 * np + 1][0], b[2 * np + 1][1], bd);
            }
#pragma unroll
            for (int mt = 0; mt < 2; mt++)
#pragma unroll
                for (int nt = 0; nt < 4; nt++)
                    MMA_F16(acc[mt][nt], a[mt], b[nt]);
        }

        if (s + 2 < NITER) {
            __syncthreads();          // all reads of this slot done
            FILL(s & 1, (s + 2) * 64);
        }
    }

#pragma unroll
    for (int mt = 0; mt < 2; mt++) {
        const int row = brow + wm * 32 + mt * 16 + (lane >> 2);
#pragma unroll
        for (int nt = 0; nt < 4; nt++) {
            const int col = bcol + wn * 32 + nt * 8 + (lane & 3) * 2;
            const float b0 = __ldg(bias + col), b1 = __ldg(bias + col + 1);
            if (OUT_HALF) {
                __half* C = (__half*)Cv;
                __half2 p0 = __floats2half2_rn(acc[mt][nt][0] + b0,
                                               acc[mt][nt][1] + b1);
                __half2 p1 = __floats2half2_rn(acc[mt][nt][2] + b0,
                                               acc[mt][nt][3] + b1);
                *(uint32_t*)&C[(size_t)row * ldc + col] = *(uint32_t*)&p0;
                *(uint32_t*)&C[(size_t)(row + 8) * ldc + col] = *(uint32_t*)&p1;
            } else {
                float* C = (float*)Cv;
                float2 o;
                o.x = acc[mt][nt][0] + b0;
                o.y = acc[mt][nt][1] + b1;
                *(float2*)&C[(size_t)row * ldc + col] = o;
                o.x = acc[mt][nt][2] + b0;
                o.y = acc[mt][nt][3] + b1;
                *(float2*)&C[(size_t)(row + 8) * ldc + col] = o;
            }
        }
    }
}

// ---------------- per-(b,h) irrep attention (R16, validated) -----------------
#define HEADB 6912
#define SS_O  (8 * HEADB)              // 55296
#define AT_SMEM (SS_O + 8 * 1088)      // 64000
#define QP    72                        // halves per row (144B pitch)

__global__ __launch_bounds__(256) void psead_attn(
    const __half* __restrict__ QKV, __half* __restrict__ Tg,
    const uint4* __restrict__ pfh, const uint4* __restrict__ pfl,
    const uint4* __restrict__ pfb)
{
    extern __shared__ __align__(16) char sm[];
    const uint32_t sb = smem_u32(sm);
    const int tid  = threadIdx.x;
    const int wid  = tid >> 5;
    const int lane = tid & 31;
    const int g    = lane >> 2;
    const int tg   = lane & 3;

    const int ghead = blockIdx.x * 8 + wid;
    const int b = ghead >> 4, h = ghead & 15;
    const size_t baseq = (size_t)(b * K_SEQ) * N3 + (size_t)h * HD;
    const size_t baset = (size_t)b * (K_SEQ * D_DIM) + (size_t)h * HD;
    const uint32_t SQ = wid * HEADB;
    const uint32_t SK = SQ + 16 * QP * 2;
    const uint32_t SV = SK + 16 * QP * 2;
#pragma unroll
    for (int t = 0; t < 4; t++) {
        const int c = lane + t * 32;
        const int row = c >> 3, cw = c & 7;
        const uint32_t so = row * (QP * 2) + cw * 16;
        const size_t go = baseq + (size_t)row * N3 + cw * 8;
        *(uint4*)(sm + SQ + so) = *(const uint4*)(QKV + go);
        *(uint4*)(sm + SK + so) = *(const uint4*)(QKV + go + GN);
        *(uint4*)(sm + SV + so) = *(const uint4*)(QKV + go + 2 * GN);
    }
    __syncwarp();

    const uint32_t lrow = (uint32_t)(lane & 15) * (QP * 2);
    const uint32_t lcol8 = (uint32_t)((lane >> 4) * 8) * 2;

    float S0[4] = {0.f, 0.f, 0.f, 0.f};
    float S1[4] = {0.f, 0.f, 0.f, 0.f};
#pragma unroll
    for (int kc = 0; kc < 4; kc++) {
        uint32_t qa0, qa1, qa2, qa3;
        ldsm4(qa0, qa1, qa2, qa3, sb + SQ + lrow + (uint32_t)(kc * 32) + lcol8);
        uint32_t kb0, kb1, kb2, kb3;
        ldsm4(kb0, kb1, kb2, kb3, sb + SK + lrow + (uint32_t)(kc * 32) + lcol8);
        MMA_S(S0, qa0, qa1, qa2, qa3, kb0, kb2);
        MMA_S(S1, qa0, qa1, qa2, qa3, kb1, kb3);
    }
    float* sS = (float*)(sm + SS_O + wid * 1088);
    sS[g * 17 + 2 * tg]             = S0[0] * 0.125f;
    sS[g * 17 + 2 * tg + 1]         = S0[1] * 0.125f;
    sS[(g + 8) * 17 + 2 * tg]       = S0[2] * 0.125f;
    sS[(g + 8) * 17 + 2 * tg + 1]   = S0[3] * 0.125f;
    sS[g * 17 + 2 * tg + 8]         = S1[0] * 0.125f;
    sS[g * 17 + 2 * tg + 9]         = S1[1] * 0.125f;
    sS[(g + 8) * 17 + 2 * tg + 8]   = S1[2] * 0.125f;
    sS[(g + 8) * 17 + 2 * tg + 9]   = S1[3] * 0.125f;
    __syncwarp();

    uint32_t sh[4], sl[4];
    {
        float x0 = sS[(2 * tg) * 17 + g],     x1 = sS[(2 * tg + 1) * 17 + g];
        float x2 = sS[(2 * tg + 8) * 17 + g], x3 = sS[(2 * tg + 9) * 17 + g];
        float y0 = sS[(2 * tg) * 17 + g + 8],     y1 = sS[(2 * tg + 1) * 17 + g + 8];
        float y2 = sS[(2 * tg + 8) * 17 + g + 8], y3 = sS[(2 * tg + 9) * 17 + g + 8];
        split2(x0, x1, sh[0], sl[0]);
        split2(x2, x3, sh[1], sl[1]);
        split2(y0, y1, sh[2], sl[2]);
        split2(y2, y3, sh[3], sl[3]);
    }

    float M0[4] = {0.f, 0.f, 0.f, 0.f};
    float M1[4] = {0.f, 0.f, 0.f, 0.f};
    for (int p = 0; p < NIRR; p++) {
        const uint4 ph = __ldg(pfh + p * 32 + lane);
        const uint4 pl = __ldg(pfl + p * 32 + lane);
        const uint4 pb = __ldg(pfb + p * 32 + lane);

        float T0[4] = {0.f, 0.f, 0.f, 0.f};
        float T1[4] = {0.f, 0.f, 0.f, 0.f};
        MMA_S(T0, ph.x, ph.y, ph.z, ph.w, sh[0], sh[1]);
        MMA_S(T1, ph.x, ph.y, ph.z, ph.w, sh[2], sh[3]);
        MMA_S(T0, ph.x, ph.y, ph.z, ph.w, sl[0], sl[1]);
        MMA_S(T1, ph.x, ph.y, ph.z, ph.w, sl[2], sl[3]);
        MMA_S(T0, pl.x, pl.y, pl.z, pl.w, sh[0], sh[1]);
        MMA_S(T1, pl.x, pl.y, pl.z, pl.w, sh[2], sh[3]);

        uint32_t tH[4], tL[4];
        split2(T0[0], T0[1], tH[0], tL[0]);
        split2(T0[2], T0[3], tH[1], tL[1]);
        split2(T1[0], T1[1], tH[2], tL[2]);
        split2(T1[2], T1[3], tH[3], tL[3]);

        float z0[4] = {0.f, 0.f, 0.f, 0.f};
        float z1[4] = {0.f, 0.f, 0.f, 0.f};
        MMA_S(z0, tH[0], tH[1], tH[2], tH[3], ph.x, ph.z);
        MMA_S(z1, tH[0], tH[1], tH[2], tH[3], ph.y, ph.w);
        MMA_S(z0, tH[0], tH[1], tH[2], tH[3], pl.x, pl.z);
        MMA_S(z1, tH[0], tH[1], tH[2], tH[3], pl.y, pl.w);
        MMA_S(z0, tL[0], tL[1], tL[2], tL[3], ph.x, ph.z);
        MMA_S(z1, tL[0], tL[1], tL[2], tL[3], ph.y, ph.w);

        const float e00 = __expf(z0[0]), e01 = __expf(z0[1]);
        const float e10 = __expf(z1[0]), e11 = __expf(z1[1]);
        const float e02 = __expf(z0[2]), e03 = __expf(z0[3]);
        const float e12 = __expf(z1[2]), e13 = __expf(z1[3]);
        float sg = e00 + e01 + e10 + e11;
        float s8 = e02 + e03 + e12 + e13;
        sg += __shfl_xor_sync(0xffffffffu, sg, 1);
        sg += __shfl_xor_sync(0xffffffffu, sg, 2);
        s8 += __shfl_xor_sync(0xffffffffu, s8, 1);
        s8 += __shfl_xor_sync(0xffffffffu, s8, 2);
        const float i0 = __frcp_rn(sg), i1 = __frcp_rn(s8);

        uint32_t w0 = pk2(e00 * i0, e01 * i0);
        uint32_t w1 = pk2(e02 * i1, e03 * i1);
        uint32_t w2 = pk2(e10 * i0, e11 * i0);
        uint32_t w3 = pk2(e12 * i1, e13 * i1);

        MMA_S(M0, w0, w1, w2, w3, pb.x, pb.y);
        MMA_S(M1, w0, w1, w2, w3, pb.z, pb.w);
    }

    uint32_t mf0 = pk2(M0[0], M0[1]);
    uint32_t mf1 = pk2(M0[2], M0[3]);
    uint32_t mf2 = pk2(M1[0], M1[1]);
    uint32_t mf3 = pk2(M1[2], M1[3]);
#pragma unroll
    for (int nc = 0; nc < 4; nc++) {
        uint32_t vb0, vb1, vb2, vb3;
        ldsm4t(vb0, vb1, vb2, vb3, sb + SV + lrow + (uint32_t)(nc * 32) + lcol8);
        float OA[4] = {0.f, 0.f, 0.f, 0.f};
        float OB[4] = {0.f, 0.f, 0.f, 0.f};
        MMA_S(OA, mf0, mf1, mf2, mf3, vb0, vb1);
        MMA_S(OB, mf0, mf1, mf2, mf3, vb2, vb3);
        __half* dst = Tg + baset;
        const int c0 = nc * 16 + 2 * tg;
        *(uint32_t*)(dst + (size_t)g * D_DIM + c0)           = pk2(OA[0], OA[1]);
        *(uint32_t*)(dst + (size_t)g * D_DIM + c0 + 8)       = pk2(OB[0], OB[1]);
        *(uint32_t*)(dst + (size_t)(g + 8) * D_DIM + c0)     = pk2(OA[2], OA[3]);
        *(uint32_t*)(dst + (size_t)(g + 8) * D_DIM + c0 + 8) = pk2(OB[2], OB[3]);
    }
}

// ---------------- launch -----------------------------------------------------
extern "C" void kernel_launch(void* const* d_in, const int* in_sizes, int n_in,
                              void* d_out, int out_size)
{
    (void)in_sizes; (void)n_in; (void)out_size;
    const float* x    = (const float*)d_in[0];
    const float* proj = (const float*)d_in[1];
    const float* Wq   = (const float*)d_in[2];
    const float* bq   = (const float*)d_in[3];
    const float* Wk   = (const float*)d_in[4];
    const float* bk   = (const float*)d_in[5];
    const float* Wv   = (const float*)d_in[6];
    const float* bv   = (const float*)d_in[7];
    const float* Wo   = (const float*)d_in[8];
    const float* bo   = (const float*)d_in[9];
    float* out = (float*)d_out;

    __half *xh, *qkv, *th, *wt;
    float* gb;
    uint4 *pfh, *pfl, *pfb;
    cudaGetSymbolAddress((void**)&xh, g_xh);
    cudaGetSymbolAddress((void**)&qkv, g_qkv);
    cudaGetSymbolAddress((void**)&th, g_th);
    cudaGetSymbolAddress((void**)&wt, g_wt);
    cudaGetSymbolAddress((void**)&gb, g_bias);
    cudaGetSymbolAddress((void**)&pfh, g_pfh);
    cudaGetSymbolAddress((void**)&pfl, g_pfl);
    cudaGetSymbolAddress((void**)&pfb, g_pfb);

    cudaFuncSetAttribute(gemm_f16<1>, cudaFuncAttributeMaxDynamicSharedMemorySize,
                         SMEM_DYN);
    cudaFuncSetAttribute(gemm_f16<0>, cudaFuncAttributeMaxDynamicSharedMemorySize,
                         SMEM_DYN);
    cudaFuncSetAttribute(psead_attn, cudaFuncAttributeMaxDynamicSharedMemorySize,
                         AT_SMEM);

    const int WSZ = GK * GN;

    // k0: ALL preparation in one launch
    prep_all<<<8193, 256>>>((const float4*)x, proj, Wq, Wk, Wv, Wo,
                            bq, bk, bv,
                            (uint2*)xh, wt, pfh, pfl, pfb, gb);
    // k1: merged QKV GEMM
    {
        dim3 gg(N3 / 64, GM / 128);   // (48, 128)
        gemm_f16<1><<<gg, 256, SMEM_DYN>>>(xh, wt, gb, qkv, N3);
    }
    // k2: attention
    psead_attn<<<B_SZ * H_NUM / 8, 256, AT_SMEM>>>(qkv, th, pfh, pfl, pfb);
    // k3: output GEMM
    {
        dim3 gg(GN / 64, GM / 128);   // (16, 128)
        gemm_f16<0><<<gg, 256, SMEM_DYN>>>(th, wt + 3 * WSZ, bo, out, GN);
    }
}